// round 7
// baseline (speedup 1.0000x reference)
#include <cuda_runtime.h>
#include <cstdint>

#define NBATCH   2048
#define CEM_S    1000
#define CEM_NE   100
#define CEM_NI   10
#define HID      128
#define KT       64                   // k-tile for smem
#define TOTAL    (NBATCH * CEM_S)     // 2,048,000
#define INIT_SIG 10.0f

// ---------------- device scratch (no allocations allowed) ----------------
__device__ float g_mu[NBATCH];
__device__ float g_sigma[NBATCH];
__device__ float g_y[TOTAL];
__device__ float g_fx[TOTAL];

// ---------------- threefry-2x32 (exact JAX, partitionable mode) ----------------
static __host__ __device__ __forceinline__ uint32_t rotl32(uint32_t v, uint32_t d) {
    return (v << d) | (v >> (32u - d));
}

static __host__ __device__ __forceinline__ void threefry2x32(
    uint32_t k0, uint32_t k1, uint32_t& x0, uint32_t& x1)
{
    uint32_t ks0 = k0, ks1 = k1, ks2 = k0 ^ k1 ^ 0x1BD11BDAu;
    x0 += ks0; x1 += ks1;
#define TF_R(r) { x0 += x1; x1 = rotl32(x1, r); x1 ^= x0; }
    TF_R(13) TF_R(15) TF_R(26) TF_R(6)   x0 += ks1; x1 += ks2 + 1u;
    TF_R(17) TF_R(29) TF_R(16) TF_R(24)  x0 += ks2; x1 += ks0 + 2u;
    TF_R(13) TF_R(15) TF_R(26) TF_R(6)   x0 += ks0; x1 += ks1 + 3u;
    TF_R(17) TF_R(29) TF_R(16) TF_R(24)  x0 += ks1; x1 += ks2 + 4u;
    TF_R(13) TF_R(15) TF_R(26) TF_R(6)   x0 += ks2; x1 += ks0 + 5u;
#undef TF_R
}

__device__ __forceinline__ uint32_t tf_bits32(uint32_t k0, uint32_t k1, uint32_t idx) {
    uint32_t x0 = 0u, x1 = idx;
    threefry2x32(k0, k1, x0, x1);
    return x0 ^ x1;
}

__device__ __forceinline__ float bits_to_normal(uint32_t bits) {
    float f = __uint_as_float((bits >> 9) | 0x3f800000u) - 1.0f;   // [0,1)
    const float lo = -0.99999994f;
    float u = fmaxf(lo, f * 2.0f + lo);
    float w = -log1pf(-u * u);
    float p;
    if (w < 5.0f) {
        w -= 2.5f;
        p = 2.81022636e-08f;
        p = fmaf(p, w, 3.43273939e-07f);
        p = fmaf(p, w, -3.5233877e-06f);
        p = fmaf(p, w, -4.39150654e-06f);
        p = fmaf(p, w, 0.00021858087f);
        p = fmaf(p, w, -0.00125372503f);
        p = fmaf(p, w, -0.00417768164f);
        p = fmaf(p, w, 0.246640727f);
        p = fmaf(p, w, 1.50140941f);
    } else {
        w = sqrtf(w) - 3.0f;
        p = -0.000200214257f;
        p = fmaf(p, w, 0.000100950558f);
        p = fmaf(p, w, 0.00134934322f);
        p = fmaf(p, w, -0.00367342844f);
        p = fmaf(p, w, 0.00573950773f);
        p = fmaf(p, w, -0.0076224613f);
        p = fmaf(p, w, 0.00943887047f);
        p = fmaf(p, w, 1.00167406f);
        p = fmaf(p, w, 2.83297682f);
    }
    return 1.4142135623730951f * (p * u);
}

// ---------------- fast tanh: 1 - 2/(e^{2x}+1), MUFU ex2 + rcp, ~1.2e-7 abs err ----------------
__device__ __forceinline__ float tanh_fast(float x) {
    float xc = fminf(fmaxf(x, -10.0f), 10.0f);
    float m  = xc * 2.8853900817779268f;   // 2 * log2(e)
    float e;
    asm("ex2.approx.f32 %0, %1;" : "=f"(e) : "f"(m));
    float den = e + 1.0f;
    float r;
    asm("rcp.approx.f32 %0, %1;" : "=f"(r) : "f"(den));
    return fmaf(-2.0f, r, 1.0f);
}

// ---------------- packed f32x2 helpers ----------------
__device__ __forceinline__ unsigned long long pack2(float lo, float hi) {
    unsigned long long r;
    asm("mov.b64 %0, {%1, %2};" : "=l"(r) : "f"(lo), "f"(hi));
    return r;
}
__device__ __forceinline__ void unpack2(unsigned long long v, float& lo, float& hi) {
    asm("mov.b64 {%0, %1}, %2;" : "=f"(lo), "=f"(hi) : "l"(v));
}
__device__ __forceinline__ unsigned long long swap2(unsigned long long v) {
    float lo, hi; unpack2(v, lo, hi);
    return pack2(hi, lo);
}
__device__ __forceinline__ void fma2(unsigned long long& d, unsigned long long a, unsigned long long b) {
    asm("fma.rn.f32x2 %0, %1, %2, %0;" : "+l"(d) : "l"(a), "l"(b));
}

// ---------------- init ----------------
__global__ void init_kernel() {
    int i = blockIdx.x * blockDim.x + threadIdx.x;
    if (i < NBATCH) { g_mu[i] = 0.0f; g_sigma[i] = INIT_SIG; }
}

// ---------------- fused sample + energy kernel ----------------
// One block = 128 candidates. 128 threads, 2 CTAs/SM.
// Per-thread tile: 16 m x 8 j. A natural m-pairs, B natural j-pairs + lane-swapped
// copies (2 FMA2 per pair-pair gives all 4 products). Fast MUFU tanh everywhere.
__global__ void __launch_bounds__(128, 2) energy_kernel(
    uint32_t k0, uint32_t k1,
    const float* __restrict__ x,  const float* __restrict__ W1, const float* __restrict__ b1,
    const float* __restrict__ W2, const float* __restrict__ b2,
    const float* __restrict__ W3, const float* __restrict__ b3)
{
    extern __shared__ float dyn[];
    float* h1t = dyn;                   // [KT*128] : h1t[k][m]
    float* W2s = dyn + KT * 128;        // [KT*128] : W2s[k][j]
    float* red = dyn;                   // alias post-GEMM: [128][17]

    __shared__ float sy[128], sxv[128];
    __shared__ float sW1a[HID], sW1b[HID], sb1[HID], sb2[HID], sW3[HID];
    __shared__ float sb3;

    const int tid = threadIdx.x;
    const int g0  = blockIdx.x * 128;

    // stage small weights
    if (tid < HID) {
        sW1a[tid] = W1[tid];
        sW1b[tid] = W1[HID + tid];
        sb1[tid]  = b1[tid];
        sb2[tid]  = b2[tid];
        sW3[tid]  = W3[tid];
    }
    if (tid == 0) sb3 = b3[0];

    // candidates: eps via threefry (partitionable), Ys = mu + sigma*eps
    {
        int g = g0 + tid;
        int b = g / CEM_S;
        float eps = bits_to_normal(tf_bits32(k0, k1, (uint32_t)g));
        float yv  = g_mu[b] + g_sigma[b] * eps;
        sy[tid]  = yv;
        sxv[tid] = x[b];
        g_y[g]   = yv;
    }
    __syncthreads();

    // thread tile: 16 m x 8 j
    const int mg = tid >> 4, jg = tid & 15;
    const int m0 = mg * 16, j0 = jg * 8;

    unsigned long long accd[8][4];   // (c[m0+2p][j0+2q],   c[m0+2p+1][j0+2q+1])
    unsigned long long accs[8][4];   // (c[m0+2p][j0+2q+1], c[m0+2p+1][j0+2q])
#pragma unroll
    for (int p = 0; p < 8; p++)
#pragma unroll
        for (int q = 0; q < 4; q++) { accd[p][q] = 0ull; accs[p][q] = 0ull; }

    for (int t = 0; t < HID / KT; t++) {
        const int kb = t * KT;

        // fill W2 tile (coalesced float4)
        {
            const float4* gw = reinterpret_cast<const float4*>(W2 + kb * 128);
            float4* sw = reinterpret_cast<float4*>(W2s);
#pragma unroll
            for (int i = tid; i < KT * 32; i += 128) sw[i] = gw[i];
        }
        // fill h1 tile: h1t[k][m] = tanh(x*W1a + y*W1b + b1)
#pragma unroll
        for (int i = tid; i < KT * 128; i += 128) {
            int m = i & 127, k = i >> 7;
            float pre = fmaf(sxv[m], sW1a[kb + k], fmaf(sy[m], sW1b[kb + k], sb1[kb + k]));
            h1t[i] = tanh_fast(pre);
        }
        __syncthreads();

#pragma unroll 2
        for (int k = 0; k < KT; k++) {
            // A: 16 natural floats = 8 adjacent-m pairs (64B)
            const ulonglong2* ar = reinterpret_cast<const ulonglong2*>(&h1t[k * 128 + m0]);
            ulonglong2 A0 = ar[0], A1 = ar[1], A2 = ar[2], A3 = ar[3];
            unsigned long long av[8] = {A0.x, A0.y, A1.x, A1.y, A2.x, A2.y, A3.x, A3.y};

            // B: 8 natural floats = 4 adjacent-j pairs (32B) + swapped copies
            const ulonglong2* br = reinterpret_cast<const ulonglong2*>(&W2s[k * 128 + j0]);
            ulonglong2 B0 = br[0], B1 = br[1];
            unsigned long long bv[4] = {B0.x, B0.y, B1.x, B1.y};
            unsigned long long sv[4] = {swap2(bv[0]), swap2(bv[1]), swap2(bv[2]), swap2(bv[3])};

#pragma unroll
            for (int p = 0; p < 8; p++)
#pragma unroll
                for (int q = 0; q < 4; q++) {
                    fma2(accd[p][q], av[p], bv[q]);
                    fma2(accs[p][q], av[p], sv[q]);
                }
        }
        __syncthreads();   // tile buffers free for rewrite ('red' alias after last tile)
    }

    // epilogue: h2 = tanh(c + b2); partial E = sum_j h2*W3
#pragma unroll
    for (int p = 0; p < 8; p++) {
        float se = 0.0f, so = 0.0f;   // rows m0+2p (even), m0+2p+1 (odd)
#pragma unroll
        for (int q = 0; q < 4; q++) {
            float d_lo, d_hi, s_lo, s_hi;
            unpack2(accd[p][q], d_lo, d_hi);
            unpack2(accs[p][q], s_lo, s_hi);
            float b2e = sb2[j0 + 2 * q],     w3e = sW3[j0 + 2 * q];
            float b2o = sb2[j0 + 2 * q + 1], w3o = sW3[j0 + 2 * q + 1];
            se = fmaf(tanh_fast(d_lo + b2e), w3e, se);
            se = fmaf(tanh_fast(s_lo + b2o), w3o, se);
            so = fmaf(tanh_fast(s_hi + b2e), w3e, so);
            so = fmaf(tanh_fast(d_hi + b2o), w3o, so);
        }
        red[(m0 + 2 * p) * 17 + jg]     = se;
        red[(m0 + 2 * p + 1) * 17 + jg] = so;
    }
    __syncthreads();

    {
        float e = 0.0f;
#pragma unroll
        for (int t = 0; t < 16; t++) e += red[tid * 17 + t];
        e += sb3;
        g_fx[g0 + tid] = e * e;
    }
}

// ---------------- per-row top-100 (exact top_k semantics: value then index) ----------------
__device__ __forceinline__ float block_reduce_512(float v, float* sred) {
    __syncthreads();
    const unsigned mask = 0xffffffffu;
#pragma unroll
    for (int o = 16; o > 0; o >>= 1) v += __shfl_down_sync(mask, v, o);
    int lane = threadIdx.x & 31, wid = threadIdx.x >> 5;
    if (lane == 0) sred[wid] = v;
    __syncthreads();
    if (wid == 0) {
        float r = (lane < 16) ? sred[lane] : 0.0f;
#pragma unroll
        for (int o = 8; o > 0; o >>= 1) r += __shfl_down_sync(mask, r, o);
        if (lane == 0) sred[16] = r;
    }
    __syncthreads();
    return sred[16];
}

__global__ void __launch_bounds__(512) topk_kernel() {
    __shared__ float skey[1024];
    __shared__ float syv[1024];
    __shared__ int   sidx[1024];
    __shared__ float sred[17];
    __shared__ float smu;

    const int tid = threadIdx.x;
    const int b   = blockIdx.x;
    const float* fx = g_fx + (size_t)b * CEM_S;
    const float* yy = g_y  + (size_t)b * CEM_S;

    for (int i = tid; i < 1024; i += 512) {
        if (i < CEM_S) { skey[i] = fx[i]; syv[i] = yy[i]; sidx[i] = i; }
        else           { skey[i] = __int_as_float(0x7f800000); syv[i] = 0.0f; sidx[i] = i; }
    }
    __syncthreads();

    for (int k = 2; k <= 1024; k <<= 1) {
        for (int j = k >> 1; j > 0; j >>= 1) {
            for (int i = tid; i < 1024; i += 512) {
                int l = i ^ j;
                if (l > i) {
                    float ki = skey[i], kl = skey[l];
                    int ii = sidx[i], il = sidx[l];
                    bool gt  = (ki > kl) || (ki == kl && ii > il);
                    bool asc = ((i & k) == 0);
                    if (gt == asc) {
                        skey[i] = kl; skey[l] = ki;
                        sidx[i] = il; sidx[l] = ii;
                        float t = syv[i]; syv[i] = syv[l]; syv[l] = t;
                    }
                }
            }
            __syncthreads();
        }
    }

    float v = (tid < CEM_NE) ? syv[tid] : 0.0f;
    float tot = block_reduce_512(v, sred);
    if (tid == 0) smu = tot / (float)CEM_NE;
    __syncthreads();
    float mu = smu;

    float d  = (tid < CEM_NE) ? (syv[tid] - mu) : 0.0f;
    float ss = block_reduce_512(d * d, sred);
    if (tid == 0) {
        g_mu[b]    = mu;
        g_sigma[b] = sqrtf(ss / (float)CEM_NE);
    }
}

// ---------------- final: yhat + diag-Gaussian samples ----------------
__global__ void sample_kernel(uint32_t k0, uint32_t k1, float* __restrict__ out) {
    int gid = blockIdx.x * blockDim.x + threadIdx.x;
    if (gid >= TOTAL) return;
    int b = gid & (NBATCH - 1);
    float eps = bits_to_normal(tf_bits32(k0, k1, (uint32_t)gid));
    float mu = g_mu[b], sg = g_sigma[b];
    float cov = sg * sg;
    cov = fminf(fmaxf(cov, 1e-3f), 100.0f);
    out[NBATCH + gid] = mu + sqrtf(cov) * eps;
    if (gid < NBATCH) out[gid] = g_mu[gid];
}

// ---------------- launch ----------------
extern "C" void kernel_launch(void* const* d_in, const int* in_sizes, int n_in,
                              void* d_out, int out_size)
{
    const float* x  = (const float*)d_in[0];
    const float* W1 = (const float*)d_in[1];
    const float* b1 = (const float*)d_in[2];
    const float* W2 = (const float*)d_in[3];
    const float* b2 = (const float*)d_in[4];
    const float* W3 = (const float*)d_in[5];
    const float* b3 = (const float*)d_in[6];
    float* out = (float*)d_out;

    // JAX partitionable-mode key derivation
    uint32_t cem0 = 0u, cem1 = 0u; threefry2x32(0u, 42u, cem0, cem1);   // split(key,2)[0]
    uint32_t smp0 = 0u, smp1 = 1u; threefry2x32(0u, 42u, smp0, smp1);   // split(key,2)[1]

    uint32_t ik0[CEM_NI], ik1[CEM_NI];
    for (int i = 0; i < CEM_NI; i++) {
        uint32_t a = 0u, c = (uint32_t)i;
        threefry2x32(cem0, cem1, a, c);
        ik0[i] = a; ik1[i] = c;
    }

    const int SMEM_BYTES = 2 * KT * HID * (int)sizeof(float);   // 64KB
    cudaFuncSetAttribute(energy_kernel, cudaFuncAttributeMaxDynamicSharedMemorySize, SMEM_BYTES);

    init_kernel<<<(NBATCH + 255) / 256, 256>>>();

    for (int i = 0; i < CEM_NI; i++) {
        energy_kernel<<<TOTAL / 128, 128, SMEM_BYTES>>>(ik0[i], ik1[i], x, W1, b1, W2, b2, W3, b3);
        topk_kernel<<<NBATCH, 512>>>();
    }

    sample_kernel<<<(TOTAL + 255) / 256, 256>>>(smp0, smp1, out);
}

// round 8
// speedup vs baseline: 1.0779x; 1.0779x over previous
#include <cuda_runtime.h>
#include <cstdint>

#define NBATCH   2048
#define CEM_S    1000
#define CEM_NE   100
#define CEM_NI   10
#define HID      128
#define KT       32                   // per-warp h1 k-tile
#define TOTAL    (NBATCH * CEM_S)     // 2,048,000
#define INIT_SIG 10.0f

// ---------------- device scratch (no allocations allowed) ----------------
__device__ float g_mu[NBATCH];
__device__ float g_sigma[NBATCH];
__device__ float g_y[TOTAL];
__device__ float g_fx[TOTAL];

// ---------------- threefry-2x32 (exact JAX, partitionable mode) ----------------
static __host__ __device__ __forceinline__ uint32_t rotl32(uint32_t v, uint32_t d) {
    return (v << d) | (v >> (32u - d));
}

static __host__ __device__ __forceinline__ void threefry2x32(
    uint32_t k0, uint32_t k1, uint32_t& x0, uint32_t& x1)
{
    uint32_t ks0 = k0, ks1 = k1, ks2 = k0 ^ k1 ^ 0x1BD11BDAu;
    x0 += ks0; x1 += ks1;
#define TF_R(r) { x0 += x1; x1 = rotl32(x1, r); x1 ^= x0; }
    TF_R(13) TF_R(15) TF_R(26) TF_R(6)   x0 += ks1; x1 += ks2 + 1u;
    TF_R(17) TF_R(29) TF_R(16) TF_R(24)  x0 += ks2; x1 += ks0 + 2u;
    TF_R(13) TF_R(15) TF_R(26) TF_R(6)   x0 += ks0; x1 += ks1 + 3u;
    TF_R(17) TF_R(29) TF_R(16) TF_R(24)  x0 += ks1; x1 += ks2 + 4u;
    TF_R(13) TF_R(15) TF_R(26) TF_R(6)   x0 += ks2; x1 += ks0 + 5u;
#undef TF_R
}

__device__ __forceinline__ uint32_t tf_bits32(uint32_t k0, uint32_t k1, uint32_t idx) {
    uint32_t x0 = 0u, x1 = idx;
    threefry2x32(k0, k1, x0, x1);
    return x0 ^ x1;
}

__device__ __forceinline__ float bits_to_normal(uint32_t bits) {
    float f = __uint_as_float((bits >> 9) | 0x3f800000u) - 1.0f;   // [0,1)
    const float lo = -0.99999994f;
    float u = fmaxf(lo, f * 2.0f + lo);
    float w = -log1pf(-u * u);
    float p;
    if (w < 5.0f) {
        w -= 2.5f;
        p = 2.81022636e-08f;
        p = fmaf(p, w, 3.43273939e-07f);
        p = fmaf(p, w, -3.5233877e-06f);
        p = fmaf(p, w, -4.39150654e-06f);
        p = fmaf(p, w, 0.00021858087f);
        p = fmaf(p, w, -0.00125372503f);
        p = fmaf(p, w, -0.00417768164f);
        p = fmaf(p, w, 0.246640727f);
        p = fmaf(p, w, 1.50140941f);
    } else {
        w = sqrtf(w) - 3.0f;
        p = -0.000200214257f;
        p = fmaf(p, w, 0.000100950558f);
        p = fmaf(p, w, 0.00134934322f);
        p = fmaf(p, w, -0.00367342844f);
        p = fmaf(p, w, 0.00573950773f);
        p = fmaf(p, w, -0.0076224613f);
        p = fmaf(p, w, 0.00943887047f);
        p = fmaf(p, w, 1.00167406f);
        p = fmaf(p, w, 2.83297682f);
    }
    return 1.4142135623730951f * (p * u);
}

// ---------------- fast tanh: 1 - 2/(e^{2x}+1), no clamp (saturates correctly) ----------------
__device__ __forceinline__ float tanh_fast(float x) {
    float m = x * 2.8853900817779268f;   // 2 * log2(e)
    float e;
    asm("ex2.approx.f32 %0, %1;" : "=f"(e) : "f"(m));
    float den = e + 1.0f;
    float r;
    asm("rcp.approx.f32 %0, %1;" : "=f"(r) : "f"(den));
    return fmaf(-2.0f, r, 1.0f);
}

// ---------------- packed f32x2 helpers ----------------
__device__ __forceinline__ unsigned long long pack2(float lo, float hi) {
    unsigned long long r;
    asm("mov.b64 %0, {%1, %2};" : "=l"(r) : "f"(lo), "f"(hi));
    return r;
}
__device__ __forceinline__ void unpack2(unsigned long long v, float& lo, float& hi) {
    asm("mov.b64 {%0, %1}, %2;" : "=f"(lo), "=f"(hi) : "l"(v));
}
__device__ __forceinline__ unsigned long long swap2(unsigned long long v) {
    float lo, hi; unpack2(v, lo, hi);
    return pack2(hi, lo);
}
__device__ __forceinline__ void fma2(unsigned long long& d, unsigned long long a, unsigned long long b) {
    asm("fma.rn.f32x2 %0, %1, %2, %0;" : "+l"(d) : "l"(a), "l"(b));
}

// ---------------- init ----------------
__global__ void init_kernel() {
    int i = blockIdx.x * blockDim.x + threadIdx.x;
    if (i < NBATCH) { g_mu[i] = 0.0f; g_sigma[i] = INIT_SIG; }
}

// ---------------- fused sample + energy kernel ----------------
// One block = 128 candidates. 128 threads, 2 CTAs/SM.
// W2 staged ONCE (full 64KB). Each warp owns h1 rows m in [32w, 32w+32): fills a
// private KTx32 tile and consumes it with only __syncwarp -> no block barriers in
// the mainloop, so one warp's MUFU/tanh fill overlaps other warps' FMA2 streams.
__global__ void __launch_bounds__(128, 2) energy_kernel(
    uint32_t k0, uint32_t k1,
    const float* __restrict__ x,  const float* __restrict__ W1, const float* __restrict__ b1,
    const float* __restrict__ W2, const float* __restrict__ b2,
    const float* __restrict__ W3, const float* __restrict__ b3)
{
    extern __shared__ float dyn[];
    float* W2full = dyn;                    // [128*128] = 64KB
    float* h1w    = dyn + HID * HID;        // [4][KT*32] = 16KB
    float* red    = dyn;                    // alias post-GEMM: [128][17]

    __shared__ float sy[128], sxv[128];
    __shared__ float sW1a[HID], sW1b[HID], sb1[HID], sb2[HID], sW3[HID];
    __shared__ float sb3;

    const int tid  = threadIdx.x;
    const int w    = tid >> 5;
    const int lane = tid & 31;
    const int g0   = blockIdx.x * 128;

    // stage small weights
    if (tid < HID) {
        sW1a[tid] = W1[tid];
        sW1b[tid] = W1[HID + tid];
        sb1[tid]  = b1[tid];
        sb2[tid]  = b2[tid];
        sW3[tid]  = W3[tid];
    }
    if (tid == 0) sb3 = b3[0];

    // stage full W2 (coalesced float4)
    {
        const float4* gw = reinterpret_cast<const float4*>(W2);
        float4* sw = reinterpret_cast<float4*>(W2full);
#pragma unroll
        for (int i = tid; i < HID * HID / 4; i += 128) sw[i] = gw[i];
    }

    // candidates: eps via threefry (partitionable), Ys = mu + sigma*eps
    {
        int g = g0 + tid;
        int b = g / CEM_S;
        float eps = bits_to_normal(tf_bits32(k0, k1, (uint32_t)g));
        float yv  = g_mu[b] + g_sigma[b] * eps;
        sy[tid]  = yv;
        sxv[tid] = x[b];
        g_y[g]   = yv;
    }
    __syncthreads();   // the ONLY pre-epilogue block barrier

    // thread tile: 16 m x 8 j;  warp w owns m in [32w, 32w+32)
    const int m0loc = (lane >> 4) << 4;       // 0 or 16 within warp's 32 rows
    const int jg    = tid & 15;
    const int j0    = jg * 8;

    // this lane's fill row (fixed for whole kernel)
    float* myh1 = h1w + w * (KT * 32);
    const int   mf = w * 32 + lane;
    const float xm = sxv[mf], ym = sy[mf];

    unsigned long long accd[8][4];
    unsigned long long accs[8][4];
#pragma unroll
    for (int p = 0; p < 8; p++)
#pragma unroll
        for (int q = 0; q < 4; q++) { accd[p][q] = 0ull; accs[p][q] = 0ull; }

    for (int t = 0; t < HID / KT; t++) {
        const int kb = t * KT;

        // fill private h1 tile: myh1[kk][lane] = tanh(x*W1a + y*W1b + b1)
#pragma unroll
        for (int kk = 0; kk < KT; kk++) {
            int k = kb + kk;
            float pre = fmaf(xm, sW1a[k], fmaf(ym, sW1b[k], sb1[k]));
            myh1[kk * 32 + lane] = tanh_fast(pre);
        }
        __syncwarp();

#pragma unroll 2
        for (int kk = 0; kk < KT; kk++) {
            // A: 16 natural floats = 8 adjacent-m pairs from the warp-private tile
            const ulonglong2* ar = reinterpret_cast<const ulonglong2*>(&myh1[kk * 32 + m0loc]);
            ulonglong2 A0 = ar[0], A1 = ar[1], A2 = ar[2], A3 = ar[3];
            unsigned long long av[8] = {A0.x, A0.y, A1.x, A1.y, A2.x, A2.y, A3.x, A3.y};

            // B: 8 natural floats = 4 adjacent-j pairs + swapped copies
            const ulonglong2* br = reinterpret_cast<const ulonglong2*>(&W2full[(kb + kk) * 128 + j0]);
            ulonglong2 B0 = br[0], B1 = br[1];
            unsigned long long bv[4] = {B0.x, B0.y, B1.x, B1.y};
            unsigned long long sv[4] = {swap2(bv[0]), swap2(bv[1]), swap2(bv[2]), swap2(bv[3])};

#pragma unroll
            for (int p = 0; p < 8; p++)
#pragma unroll
                for (int q = 0; q < 4; q++) {
                    fma2(accd[p][q], av[p], bv[q]);
                    fma2(accs[p][q], av[p], sv[q]);
                }
        }
        __syncwarp();   // tile consumed; safe to refill next iteration
    }
    __syncthreads();    // all warps done with W2full; 'red' alias becomes safe

    // epilogue: h2 = tanh(c + b2); partial E = sum_j h2*W3
    const int m0g = w * 32 + m0loc;
#pragma unroll
    for (int p = 0; p < 8; p++) {
        float se = 0.0f, so = 0.0f;   // rows m0g+2p (even), m0g+2p+1 (odd)
#pragma unroll
        for (int q = 0; q < 4; q++) {
            float d_lo, d_hi, s_lo, s_hi;
            unpack2(accd[p][q], d_lo, d_hi);
            unpack2(accs[p][q], s_lo, s_hi);
            float b2e = sb2[j0 + 2 * q],     w3e = sW3[j0 + 2 * q];
            float b2o = sb2[j0 + 2 * q + 1], w3o = sW3[j0 + 2 * q + 1];
            se = fmaf(tanh_fast(d_lo + b2e), w3e, se);
            se = fmaf(tanh_fast(s_lo + b2o), w3o, se);
            so = fmaf(tanh_fast(s_hi + b2e), w3e, so);
            so = fmaf(tanh_fast(d_hi + b2o), w3o, so);
        }
        red[(m0g + 2 * p) * 17 + jg]     = se;
        red[(m0g + 2 * p + 1) * 17 + jg] = so;
    }
    __syncthreads();

    {
        float e = 0.0f;
#pragma unroll
        for (int t = 0; t < 16; t++) e += red[tid * 17 + t];
        e += sb3;
        g_fx[g0 + tid] = e * e;
    }
}

// ---------------- per-row top-100 (exact top_k semantics: value then index) ----------------
__device__ __forceinline__ float block_reduce_512(float v, float* sred) {
    __syncthreads();
    const unsigned mask = 0xffffffffu;
#pragma unroll
    for (int o = 16; o > 0; o >>= 1) v += __shfl_down_sync(mask, v, o);
    int lane = threadIdx.x & 31, wid = threadIdx.x >> 5;
    if (lane == 0) sred[wid] = v;
    __syncthreads();
    if (wid == 0) {
        float r = (lane < 16) ? sred[lane] : 0.0f;
#pragma unroll
        for (int o = 8; o > 0; o >>= 1) r += __shfl_down_sync(mask, r, o);
        if (lane == 0) sred[16] = r;
    }
    __syncthreads();
    return sred[16];
}

__global__ void __launch_bounds__(512) topk_kernel() {
    __shared__ float skey[1024];
    __shared__ float syv[1024];
    __shared__ int   sidx[1024];
    __shared__ float sred[17];
    __shared__ float smu;

    const int tid = threadIdx.x;
    const int b   = blockIdx.x;
    const float* fx = g_fx + (size_t)b * CEM_S;
    const float* yy = g_y  + (size_t)b * CEM_S;

    for (int i = tid; i < 1024; i += 512) {
        if (i < CEM_S) { skey[i] = fx[i]; syv[i] = yy[i]; sidx[i] = i; }
        else           { skey[i] = __int_as_float(0x7f800000); syv[i] = 0.0f; sidx[i] = i; }
    }
    __syncthreads();

    for (int k = 2; k <= 1024; k <<= 1) {
        for (int j = k >> 1; j > 0; j >>= 1) {
            for (int i = tid; i < 1024; i += 512) {
                int l = i ^ j;
                if (l > i) {
                    float ki = skey[i], kl = skey[l];
                    int ii = sidx[i], il = sidx[l];
                    bool gt  = (ki > kl) || (ki == kl && ii > il);
                    bool asc = ((i & k) == 0);
                    if (gt == asc) {
                        skey[i] = kl; skey[l] = ki;
                        sidx[i] = il; sidx[l] = ii;
                        float t = syv[i]; syv[i] = syv[l]; syv[l] = t;
                    }
                }
            }
            __syncthreads();
        }
    }

    float v = (tid < CEM_NE) ? syv[tid] : 0.0f;
    float tot = block_reduce_512(v, sred);
    if (tid == 0) smu = tot / (float)CEM_NE;
    __syncthreads();
    float mu = smu;

    float d  = (tid < CEM_NE) ? (syv[tid] - mu) : 0.0f;
    float ss = block_reduce_512(d * d, sred);
    if (tid == 0) {
        g_mu[b]    = mu;
        g_sigma[b] = sqrtf(ss / (float)CEM_NE);
    }
}

// ---------------- final: yhat + diag-Gaussian samples ----------------
__global__ void sample_kernel(uint32_t k0, uint32_t k1, float* __restrict__ out) {
    int gid = blockIdx.x * blockDim.x + threadIdx.x;
    if (gid >= TOTAL) return;
    int b = gid & (NBATCH - 1);
    float eps = bits_to_normal(tf_bits32(k0, k1, (uint32_t)gid));
    float mu = g_mu[b], sg = g_sigma[b];
    float cov = sg * sg;
    cov = fminf(fmaxf(cov, 1e-3f), 100.0f);
    out[NBATCH + gid] = mu + sqrtf(cov) * eps;
    if (gid < NBATCH) out[gid] = g_mu[gid];
}

// ---------------- launch ----------------
extern "C" void kernel_launch(void* const* d_in, const int* in_sizes, int n_in,
                              void* d_out, int out_size)
{
    const float* x  = (const float*)d_in[0];
    const float* W1 = (const float*)d_in[1];
    const float* b1 = (const float*)d_in[2];
    const float* W2 = (const float*)d_in[3];
    const float* b2 = (const float*)d_in[4];
    const float* W3 = (const float*)d_in[5];
    const float* b3 = (const float*)d_in[6];
    float* out = (float*)d_out;

    // JAX partitionable-mode key derivation
    uint32_t cem0 = 0u, cem1 = 0u; threefry2x32(0u, 42u, cem0, cem1);   // split(key,2)[0]
    uint32_t smp0 = 0u, smp1 = 1u; threefry2x32(0u, 42u, smp0, smp1);   // split(key,2)[1]

    uint32_t ik0[CEM_NI], ik1[CEM_NI];
    for (int i = 0; i < CEM_NI; i++) {
        uint32_t a = 0u, c = (uint32_t)i;
        threefry2x32(cem0, cem1, a, c);
        ik0[i] = a; ik1[i] = c;
    }

    const int SMEM_BYTES = (HID * HID + 4 * KT * 32) * (int)sizeof(float);   // 64KB + 16KB
    cudaFuncSetAttribute(energy_kernel, cudaFuncAttributeMaxDynamicSharedMemorySize, SMEM_BYTES);

    init_kernel<<<(NBATCH + 255) / 256, 256>>>();

    for (int i = 0; i < CEM_NI; i++) {
        energy_kernel<<<TOTAL / 128, 128, SMEM_BYTES>>>(ik0[i], ik1[i], x, W1, b1, W2, b2, W3, b3);
        topk_kernel<<<NBATCH, 512>>>();
    }

    sample_kernel<<<(TOTAL + 255) / 256, 256>>>(smp0, smp1, out);
}

// round 9
// speedup vs baseline: 1.1187x; 1.0378x over previous
#include <cuda_runtime.h>
#include <cstdint>

#define NBATCH   2048
#define CEM_S    1000
#define CEM_NE   100
#define CEM_NI   10
#define HID      128
#define KT       32                   // per-warp h1 k-tile
#define TOTAL    (NBATCH * CEM_S)     // 2,048,000
#define INIT_SIG 10.0f

// ---------------- device scratch (no allocations allowed) ----------------
__device__ float g_mu[NBATCH];
__device__ float g_sigma[NBATCH];
__device__ float g_y[TOTAL];
__device__ float g_fx[TOTAL];

// ---------------- threefry-2x32 (exact JAX, partitionable mode) ----------------
static __host__ __device__ __forceinline__ uint32_t rotl32(uint32_t v, uint32_t d) {
    return (v << d) | (v >> (32u - d));
}

static __host__ __device__ __forceinline__ void threefry2x32(
    uint32_t k0, uint32_t k1, uint32_t& x0, uint32_t& x1)
{
    uint32_t ks0 = k0, ks1 = k1, ks2 = k0 ^ k1 ^ 0x1BD11BDAu;
    x0 += ks0; x1 += ks1;
#define TF_R(r) { x0 += x1; x1 = rotl32(x1, r); x1 ^= x0; }
    TF_R(13) TF_R(15) TF_R(26) TF_R(6)   x0 += ks1; x1 += ks2 + 1u;
    TF_R(17) TF_R(29) TF_R(16) TF_R(24)  x0 += ks2; x1 += ks0 + 2u;
    TF_R(13) TF_R(15) TF_R(26) TF_R(6)   x0 += ks0; x1 += ks1 + 3u;
    TF_R(17) TF_R(29) TF_R(16) TF_R(24)  x0 += ks1; x1 += ks2 + 4u;
    TF_R(13) TF_R(15) TF_R(26) TF_R(6)   x0 += ks2; x1 += ks0 + 5u;
#undef TF_R
}

__device__ __forceinline__ uint32_t tf_bits32(uint32_t k0, uint32_t k1, uint32_t idx) {
    uint32_t x0 = 0u, x1 = idx;
    threefry2x32(k0, k1, x0, x1);
    return x0 ^ x1;
}

__device__ __forceinline__ float bits_to_normal(uint32_t bits) {
    float f = __uint_as_float((bits >> 9) | 0x3f800000u) - 1.0f;   // [0,1)
    const float lo = -0.99999994f;
    float u = fmaxf(lo, f * 2.0f + lo);
    float w = -log1pf(-u * u);
    float p;
    if (w < 5.0f) {
        w -= 2.5f;
        p = 2.81022636e-08f;
        p = fmaf(p, w, 3.43273939e-07f);
        p = fmaf(p, w, -3.5233877e-06f);
        p = fmaf(p, w, -4.39150654e-06f);
        p = fmaf(p, w, 0.00021858087f);
        p = fmaf(p, w, -0.00125372503f);
        p = fmaf(p, w, -0.00417768164f);
        p = fmaf(p, w, 0.246640727f);
        p = fmaf(p, w, 1.50140941f);
    } else {
        w = sqrtf(w) - 3.0f;
        p = -0.000200214257f;
        p = fmaf(p, w, 0.000100950558f);
        p = fmaf(p, w, 0.00134934322f);
        p = fmaf(p, w, -0.00367342844f);
        p = fmaf(p, w, 0.00573950773f);
        p = fmaf(p, w, -0.0076224613f);
        p = fmaf(p, w, 0.00943887047f);
        p = fmaf(p, w, 1.00167406f);
        p = fmaf(p, w, 2.83297682f);
    }
    return 1.4142135623730951f * (p * u);
}

// ---------------- fast tanh: 1 - 2/(e^{2x}+1), MUFU ex2 + rcp ----------------
__device__ __forceinline__ float tanh_fast(float x) {
    float m = x * 2.8853900817779268f;   // 2 * log2(e)
    float e;
    asm("ex2.approx.f32 %0, %1;" : "=f"(e) : "f"(m));
    float den = e + 1.0f;
    float r;
    asm("rcp.approx.f32 %0, %1;" : "=f"(r) : "f"(den));
    return fmaf(-2.0f, r, 1.0f);
}

// ---------------- packed f32x2 helpers ----------------
__device__ __forceinline__ unsigned long long pack2(float lo, float hi) {
    unsigned long long r;
    asm("mov.b64 %0, {%1, %2};" : "=l"(r) : "f"(lo), "f"(hi));
    return r;
}
__device__ __forceinline__ void unpack2(unsigned long long v, float& lo, float& hi) {
    asm("mov.b64 {%0, %1}, %2;" : "=f"(lo), "=f"(hi) : "l"(v));
}
__device__ __forceinline__ unsigned long long swap2(unsigned long long v) {
    float lo, hi; unpack2(v, lo, hi);
    return pack2(hi, lo);
}
__device__ __forceinline__ void fma2(unsigned long long& d, unsigned long long a, unsigned long long b) {
    asm("fma.rn.f32x2 %0, %1, %2, %0;" : "+l"(d) : "l"(a), "l"(b));
}

// ---------------- init ----------------
__global__ void init_kernel() {
    int i = blockIdx.x * blockDim.x + threadIdx.x;
    if (i < NBATCH) { g_mu[i] = 0.0f; g_sigma[i] = INIT_SIG; }
}

// ---------------- fused sample + energy kernel ----------------
// One block = 128 candidates. 256 threads (8 warps), 2 CTAs/SM -> 4 warps/SMSP.
// Thread tile: 8m x 8j (acc = 32 ull = 64 regs). Warp w owns m in [16w, 16w+16):
// fills a private KTx16 h1 tile (each lane has a fixed row, alternating k) and
// consumes it with only __syncwarp. W2 staged once in full.
__global__ void __launch_bounds__(256, 2) energy_kernel(
    uint32_t k0, uint32_t k1,
    const float* __restrict__ x,  const float* __restrict__ W1, const float* __restrict__ b1,
    const float* __restrict__ W2, const float* __restrict__ b2,
    const float* __restrict__ W3, const float* __restrict__ b3)
{
    extern __shared__ float dyn[];
    float* W2full = dyn;                    // [128*128] = 64KB
    float* h1w    = dyn + HID * HID;        // [8][KT*16] = 16KB
    float* red    = dyn;                    // alias post-GEMM: [128][17]

    __shared__ float sy[128], sxv[128];
    __shared__ float sW1a[HID], sW1b[HID], sb1[HID], sb2[HID], sW3[HID];
    __shared__ float sb3;

    const int tid  = threadIdx.x;
    const int w    = tid >> 5;
    const int lane = tid & 31;
    const int g0   = blockIdx.x * 128;

    // stage small weights
    if (tid < HID) {
        sW1a[tid] = W1[tid];
        sW1b[tid] = W1[HID + tid];
        sb1[tid]  = b1[tid];
        sb2[tid]  = b2[tid];
        sW3[tid]  = W3[tid];
    }
    if (tid == 0) sb3 = b3[0];

    // stage full W2 (coalesced float4)
    {
        const float4* gw = reinterpret_cast<const float4*>(W2);
        float4* sw = reinterpret_cast<float4*>(W2full);
#pragma unroll
        for (int i = tid; i < HID * HID / 4; i += 256) sw[i] = gw[i];
    }

    // candidates: eps via threefry (partitionable), Ys = mu + sigma*eps
    if (tid < 128) {
        int g = g0 + tid;
        int b = g / CEM_S;
        float eps = bits_to_normal(tf_bits32(k0, k1, (uint32_t)g));
        float yv  = g_mu[b] + g_sigma[b] * eps;
        sy[tid]  = yv;
        sxv[tid] = x[b];
        g_y[g]   = yv;
    }
    __syncthreads();   // the ONLY pre-epilogue block barrier

    // thread tile: 8 m x 8 j; warp w owns m in [16w, 16w+16)
    const int mg = tid >> 4, jg = tid & 15;
    const int m0loc = (mg & 1) * 8;           // 0 or 8 within warp's 16 rows
    const int j0    = jg * 8;

    // this lane's fixed fill row + k-parity
    float* myh1 = h1w + w * (KT * 16);
    const int   half = lane >> 4;             // handles kk = half, half+2, ...
    const int   mloc = lane & 15;
    const int   mf   = 16 * w + mloc;
    const float xm = sxv[mf], ym = sy[mf];

    unsigned long long accd[4][4];
    unsigned long long accs[4][4];
#pragma unroll
    for (int p = 0; p < 4; p++)
#pragma unroll
        for (int q = 0; q < 4; q++) { accd[p][q] = 0ull; accs[p][q] = 0ull; }

    for (int t = 0; t < HID / KT; t++) {
        const int kb = t * KT;

        // fill private h1 tile: myh1[kk][mloc] = tanh(x*W1a + y*W1b + b1)
#pragma unroll
        for (int kk = half; kk < KT; kk += 2) {
            int k = kb + kk;
            float pre = fmaf(xm, sW1a[k], fmaf(ym, sW1b[k], sb1[k]));
            myh1[kk * 16 + mloc] = tanh_fast(pre);
        }
        __syncwarp();

#pragma unroll 2
        for (int kk = 0; kk < KT; kk++) {
            // A: 8 natural floats = 4 adjacent-m pairs from warp-private tile
            const ulonglong2* ar = reinterpret_cast<const ulonglong2*>(&myh1[kk * 16 + m0loc]);
            ulonglong2 A0 = ar[0], A1 = ar[1];
            unsigned long long av[4] = {A0.x, A0.y, A1.x, A1.y};

            // B: 8 natural floats = 4 adjacent-j pairs + swapped copies
            const ulonglong2* br = reinterpret_cast<const ulonglong2*>(&W2full[(kb + kk) * 128 + j0]);
            ulonglong2 B0 = br[0], B1 = br[1];
            unsigned long long bv[4] = {B0.x, B0.y, B1.x, B1.y};
            unsigned long long sv[4] = {swap2(bv[0]), swap2(bv[1]), swap2(bv[2]), swap2(bv[3])};

#pragma unroll
            for (int p = 0; p < 4; p++)
#pragma unroll
                for (int q = 0; q < 4; q++) {
                    fma2(accd[p][q], av[p], bv[q]);
                    fma2(accs[p][q], av[p], sv[q]);
                }
        }
        __syncwarp();   // tile consumed; safe to refill next iteration
    }
    __syncthreads();    // all warps done with W2full; 'red' alias becomes safe

    // epilogue: h2 = tanh(c + b2); partial E = sum_j h2*W3
    const int m0g = 16 * w + m0loc;
#pragma unroll
    for (int p = 0; p < 4; p++) {
        float se = 0.0f, so = 0.0f;   // rows m0g+2p (even), m0g+2p+1 (odd)
#pragma unroll
        for (int q = 0; q < 4; q++) {
            float d_lo, d_hi, s_lo, s_hi;
            unpack2(accd[p][q], d_lo, d_hi);
            unpack2(accs[p][q], s_lo, s_hi);
            float b2e = sb2[j0 + 2 * q],     w3e = sW3[j0 + 2 * q];
            float b2o = sb2[j0 + 2 * q + 1], w3o = sW3[j0 + 2 * q + 1];
            se = fmaf(tanh_fast(d_lo + b2e), w3e, se);
            se = fmaf(tanh_fast(s_lo + b2o), w3o, se);
            so = fmaf(tanh_fast(s_hi + b2e), w3e, so);
            so = fmaf(tanh_fast(d_hi + b2o), w3o, so);
        }
        red[(m0g + 2 * p) * 17 + jg]     = se;
        red[(m0g + 2 * p + 1) * 17 + jg] = so;
    }
    __syncthreads();

    if (tid < 128) {
        float e = 0.0f;
#pragma unroll
        for (int t = 0; t < 16; t++) e += red[tid * 17 + t];
        e += sb3;
        g_fx[g0 + tid] = e * e;
    }
}

// ---------------- per-row top-100 (exact top_k semantics: value then index) ----------------
__device__ __forceinline__ float block_reduce_512(float v, float* sred) {
    __syncthreads();
    const unsigned mask = 0xffffffffu;
#pragma unroll
    for (int o = 16; o > 0; o >>= 1) v += __shfl_down_sync(mask, v, o);
    int lane = threadIdx.x & 31, wid = threadIdx.x >> 5;
    if (lane == 0) sred[wid] = v;
    __syncthreads();
    if (wid == 0) {
        float r = (lane < 16) ? sred[lane] : 0.0f;
#pragma unroll
        for (int o = 8; o > 0; o >>= 1) r += __shfl_down_sync(mask, r, o);
        if (lane == 0) sred[16] = r;
    }
    __syncthreads();
    return sred[16];
}

__global__ void __launch_bounds__(512) topk_kernel() {
    __shared__ float skey[1024];
    __shared__ float syv[1024];
    __shared__ int   sidx[1024];
    __shared__ float sred[17];
    __shared__ float smu;

    const int tid = threadIdx.x;
    const int b   = blockIdx.x;
    const float* fx = g_fx + (size_t)b * CEM_S;
    const float* yy = g_y  + (size_t)b * CEM_S;

    for (int i = tid; i < 1024; i += 512) {
        if (i < CEM_S) { skey[i] = fx[i]; syv[i] = yy[i]; sidx[i] = i; }
        else           { skey[i] = __int_as_float(0x7f800000); syv[i] = 0.0f; sidx[i] = i; }
    }
    __syncthreads();

    for (int k = 2; k <= 1024; k <<= 1) {
        for (int j = k >> 1; j > 0; j >>= 1) {
            for (int i = tid; i < 1024; i += 512) {
                int l = i ^ j;
                if (l > i) {
                    float ki = skey[i], kl = skey[l];
                    int ii = sidx[i], il = sidx[l];
                    bool gt  = (ki > kl) || (ki == kl && ii > il);
                    bool asc = ((i & k) == 0);
                    if (gt == asc) {
                        skey[i] = kl; skey[l] = ki;
                        sidx[i] = il; sidx[l] = ii;
                        float t = syv[i]; syv[i] = syv[l]; syv[l] = t;
                    }
                }
            }
            __syncthreads();
        }
    }

    float v = (tid < CEM_NE) ? syv[tid] : 0.0f;
    float tot = block_reduce_512(v, sred);
    if (tid == 0) smu = tot / (float)CEM_NE;
    __syncthreads();
    float mu = smu;

    float d  = (tid < CEM_NE) ? (syv[tid] - mu) : 0.0f;
    float ss = block_reduce_512(d * d, sred);
    if (tid == 0) {
        g_mu[b]    = mu;
        g_sigma[b] = sqrtf(ss / (float)CEM_NE);
    }
}

// ---------------- final: yhat + diag-Gaussian samples ----------------
__global__ void sample_kernel(uint32_t k0, uint32_t k1, float* __restrict__ out) {
    int gid = blockIdx.x * blockDim.x + threadIdx.x;
    if (gid >= TOTAL) return;
    int b = gid & (NBATCH - 1);
    float eps = bits_to_normal(tf_bits32(k0, k1, (uint32_t)gid));
    float mu = g_mu[b], sg = g_sigma[b];
    float cov = sg * sg;
    cov = fminf(fmaxf(cov, 1e-3f), 100.0f);
    out[NBATCH + gid] = mu + sqrtf(cov) * eps;
    if (gid < NBATCH) out[gid] = g_mu[gid];
}

// ---------------- launch ----------------
extern "C" void kernel_launch(void* const* d_in, const int* in_sizes, int n_in,
                              void* d_out, int out_size)
{
    const float* x  = (const float*)d_in[0];
    const float* W1 = (const float*)d_in[1];
    const float* b1 = (const float*)d_in[2];
    const float* W2 = (const float*)d_in[3];
    const float* b2 = (const float*)d_in[4];
    const float* W3 = (const float*)d_in[5];
    const float* b3 = (const float*)d_in[6];
    float* out = (float*)d_out;

    // JAX partitionable-mode key derivation
    uint32_t cem0 = 0u, cem1 = 0u; threefry2x32(0u, 42u, cem0, cem1);   // split(key,2)[0]
    uint32_t smp0 = 0u, smp1 = 1u; threefry2x32(0u, 42u, smp0, smp1);   // split(key,2)[1]

    uint32_t ik0[CEM_NI], ik1[CEM_NI];
    for (int i = 0; i < CEM_NI; i++) {
        uint32_t a = 0u, c = (uint32_t)i;
        threefry2x32(cem0, cem1, a, c);
        ik0[i] = a; ik1[i] = c;
    }

    const int SMEM_BYTES = (HID * HID + 8 * KT * 16) * (int)sizeof(float);   // 64KB + 16KB
    cudaFuncSetAttribute(energy_kernel, cudaFuncAttributeMaxDynamicSharedMemorySize, SMEM_BYTES);

    init_kernel<<<(NBATCH + 255) / 256, 256>>>();

    for (int i = 0; i < CEM_NI; i++) {
        energy_kernel<<<TOTAL / 128, 256, SMEM_BYTES>>>(ik0[i], ik1[i], x, W1, b1, W2, b2, W3, b3);
        topk_kernel<<<NBATCH, 512>>>();
    }

    sample_kernel<<<(TOTAL + 255) / 256, 256>>>(smp0, smp1, out);
}

// round 10
// speedup vs baseline: 2.5632x; 2.2914x over previous
#include <cuda_runtime.h>
#include <cuda_bf16.h>
#include <cstdint>

#define NBATCH   2048
#define CEM_S    1000
#define CEM_NE   100
#define CEM_NI   10
#define HID      128
#define BTP      136                  // padded k-row length for B^T tiles (bank-spread)
#define TOTAL    (NBATCH * CEM_S)     // 2,048,000
#define INIT_SIG 10.0f

// ---------------- device scratch (no allocations allowed) ----------------
__device__ float g_mu[NBATCH];
__device__ float g_sigma[NBATCH];
__device__ float g_y[TOTAL];
__device__ float g_fx[TOTAL];
// W2^T split into bf16 hi/lo: [j][k] with row pad BTP
__device__ __align__(16) uint16_t g_BThi[HID * BTP];
__device__ __align__(16) uint16_t g_BTlo[HID * BTP];

// ---------------- threefry-2x32 (exact JAX, partitionable mode) ----------------
static __host__ __device__ __forceinline__ uint32_t rotl32(uint32_t v, uint32_t d) {
    return (v << d) | (v >> (32u - d));
}

static __host__ __device__ __forceinline__ void threefry2x32(
    uint32_t k0, uint32_t k1, uint32_t& x0, uint32_t& x1)
{
    uint32_t ks0 = k0, ks1 = k1, ks2 = k0 ^ k1 ^ 0x1BD11BDAu;
    x0 += ks0; x1 += ks1;
#define TF_R(r) { x0 += x1; x1 = rotl32(x1, r); x1 ^= x0; }
    TF_R(13) TF_R(15) TF_R(26) TF_R(6)   x0 += ks1; x1 += ks2 + 1u;
    TF_R(17) TF_R(29) TF_R(16) TF_R(24)  x0 += ks2; x1 += ks0 + 2u;
    TF_R(13) TF_R(15) TF_R(26) TF_R(6)   x0 += ks0; x1 += ks1 + 3u;
    TF_R(17) TF_R(29) TF_R(16) TF_R(24)  x0 += ks1; x1 += ks2 + 4u;
    TF_R(13) TF_R(15) TF_R(26) TF_R(6)   x0 += ks2; x1 += ks0 + 5u;
#undef TF_R
}

__device__ __forceinline__ uint32_t tf_bits32(uint32_t k0, uint32_t k1, uint32_t idx) {
    uint32_t x0 = 0u, x1 = idx;
    threefry2x32(k0, k1, x0, x1);
    return x0 ^ x1;
}

__device__ __forceinline__ float bits_to_normal(uint32_t bits) {
    float f = __uint_as_float((bits >> 9) | 0x3f800000u) - 1.0f;   // [0,1)
    const float lo = -0.99999994f;
    float u = fmaxf(lo, f * 2.0f + lo);
    float w = -log1pf(-u * u);
    float p;
    if (w < 5.0f) {
        w -= 2.5f;
        p = 2.81022636e-08f;
        p = fmaf(p, w, 3.43273939e-07f);
        p = fmaf(p, w, -3.5233877e-06f);
        p = fmaf(p, w, -4.39150654e-06f);
        p = fmaf(p, w, 0.00021858087f);
        p = fmaf(p, w, -0.00125372503f);
        p = fmaf(p, w, -0.00417768164f);
        p = fmaf(p, w, 0.246640727f);
        p = fmaf(p, w, 1.50140941f);
    } else {
        w = sqrtf(w) - 3.0f;
        p = -0.000200214257f;
        p = fmaf(p, w, 0.000100950558f);
        p = fmaf(p, w, 0.00134934322f);
        p = fmaf(p, w, -0.00367342844f);
        p = fmaf(p, w, 0.00573950773f);
        p = fmaf(p, w, -0.0076224613f);
        p = fmaf(p, w, 0.00943887047f);
        p = fmaf(p, w, 1.00167406f);
        p = fmaf(p, w, 2.83297682f);
    }
    return 1.4142135623730951f * (p * u);
}

// ---------------- fast tanh: 1 - 2/(e^{2x}+1), MUFU ex2 + rcp ----------------
__device__ __forceinline__ float tanh_fast(float x) {
    float m = x * 2.8853900817779268f;   // 2 * log2(e)
    float e;
    asm("ex2.approx.f32 %0, %1;" : "=f"(e) : "f"(m));
    float den = e + 1.0f;
    float r;
    asm("rcp.approx.f32 %0, %1;" : "=f"(r) : "f"(den));
    return fmaf(-2.0f, r, 1.0f);
}

// ---------------- bf16 mma helper ----------------
__device__ __forceinline__ void mma_bf16(float* d, const uint32_t* a, uint32_t b0, uint32_t b1) {
    asm volatile(
        "mma.sync.aligned.m16n8k16.row.col.f32.bf16.bf16.f32 "
        "{%0,%1,%2,%3}, {%4,%5,%6,%7}, {%8,%9}, {%0,%1,%2,%3};"
        : "+f"(d[0]), "+f"(d[1]), "+f"(d[2]), "+f"(d[3])
        : "r"(a[0]), "r"(a[1]), "r"(a[2]), "r"(a[3]), "r"(b0), "r"(b1));
}

// compute h1 for (x,y) at k and k+1; emit packed bf16 hi-pair and lo-pair
__device__ __forceinline__ void h1pair(
    float x, float y, int k,
    const float* sW1a, const float* sW1b, const float* sb1,
    uint32_t& ah, uint32_t& al)
{
    float v0 = tanh_fast(fmaf(x, sW1a[k],     fmaf(y, sW1b[k],     sb1[k])));
    float v1 = tanh_fast(fmaf(x, sW1a[k + 1], fmaf(y, sW1b[k + 1], sb1[k + 1])));
    __nv_bfloat16 h0 = __float2bfloat16(v0);
    __nv_bfloat16 h1 = __float2bfloat16(v1);
    __nv_bfloat16 l0 = __float2bfloat16(v0 - __bfloat162float(h0));
    __nv_bfloat16 l1 = __float2bfloat16(v1 - __bfloat162float(h1));
    ah = (uint32_t)__bfloat16_as_ushort(h0) | ((uint32_t)__bfloat16_as_ushort(h1) << 16);
    al = (uint32_t)__bfloat16_as_ushort(l0) | ((uint32_t)__bfloat16_as_ushort(l1) << 16);
}

// ---------------- prep: W2 -> bf16 hi/lo transposed padded images ----------------
__global__ void w2prep_kernel(const float* __restrict__ W2) {
    int i = blockIdx.x * blockDim.x + threadIdx.x;   // i = k*128 + j
    if (i >= HID * HID) return;
    int k = i >> 7, j = i & 127;
    float v = W2[i];
    __nv_bfloat16 hb = __float2bfloat16(v);
    __nv_bfloat16 lb = __float2bfloat16(v - __bfloat162float(hb));
    g_BThi[j * BTP + k] = __bfloat16_as_ushort(hb);
    g_BTlo[j * BTP + k] = __bfloat16_as_ushort(lb);
}

// ---------------- init ----------------
__global__ void init_kernel() {
    int i = blockIdx.x * blockDim.x + threadIdx.x;
    if (i < NBATCH) { g_mu[i] = 0.0f; g_sigma[i] = INIT_SIG; }
}

// ---------------- fused sample + energy kernel (mma.sync bf16 3-term split) ----------------
// One block = 128 candidates. 256 threads (8 warps), 2 CTAs/SM.
// Warp w computes rows m in [16w, 16w+16) x all 128 j. A fragments are computed
// in registers (tanh + split, zero smem); B^T hi/lo tiles staged once per CTA.
__global__ void __launch_bounds__(256, 2) energy_kernel(
    uint32_t k0, uint32_t k1,
    const float* __restrict__ x,  const float* __restrict__ W1, const float* __restrict__ b1,
    const float* __restrict__ b2, const float* __restrict__ W3, const float* __restrict__ b3)
{
    extern __shared__ uint16_t btile[];
    uint16_t* bthi = btile;                  // [128 * BTP]
    uint16_t* btlo = btile + HID * BTP;      // [128 * BTP]

    __shared__ float sy[128], sxv[128];
    __shared__ float sW1a[HID], sW1b[HID], sb1[HID], sb2[HID], sW3[HID];
    __shared__ float sb3;

    const int tid  = threadIdx.x;
    const int w    = tid >> 5;
    const int lane = tid & 31;
    const int g0   = blockIdx.x * 128;

    // stage B^T hi/lo images (linear uint4 copy; 2176 uint4 each)
    {
        const uint4* gh = reinterpret_cast<const uint4*>(g_BThi);
        const uint4* gl = reinterpret_cast<const uint4*>(g_BTlo);
        uint4* sh = reinterpret_cast<uint4*>(bthi);
        uint4* sl = reinterpret_cast<uint4*>(btlo);
#pragma unroll
        for (int i = tid; i < HID * BTP / 8; i += 256) { sh[i] = gh[i]; sl[i] = gl[i]; }
    }

    // stage small weights
    if (tid < HID) {
        sW1a[tid] = W1[tid];
        sW1b[tid] = W1[HID + tid];
        sb1[tid]  = b1[tid];
        sb2[tid]  = b2[tid];
        sW3[tid]  = W3[tid];
    }
    if (tid == 0) sb3 = b3[0];

    // candidates: eps via threefry (partitionable), Ys = mu + sigma*eps
    if (tid < 128) {
        int g = g0 + tid;
        int b = g / CEM_S;
        float eps = bits_to_normal(tf_bits32(k0, k1, (uint32_t)g));
        float yv  = g_mu[b] + g_sigma[b] * eps;
        sy[tid]  = yv;
        sxv[tid] = x[b];
        g_y[g]   = yv;
    }
    __syncthreads();

    // fragment coordinates
    const int qr = lane >> 2;       // 0..7 : row-in-tile / B column selector
    const int qc = lane & 3;        // 0..3 : k-pair selector
    const int mr = 16 * w + qr;     // rows mr, mr+8
    const float x0v = sxv[mr],     y0v = sy[mr];
    const float x1v = sxv[mr + 8], y1v = sy[mr + 8];

    float acc[16][4];
#pragma unroll
    for (int jt = 0; jt < 16; jt++)
#pragma unroll
        for (int c = 0; c < 4; c++) acc[jt][c] = 0.0f;

#pragma unroll
    for (int s = 0; s < 8; s++) {
        const int kb = 16 * s + qc * 2;

        // A fragments (hi & lo), computed in registers
        uint32_t ah[4], al[4];
        h1pair(x0v, y0v, kb,     sW1a, sW1b, sb1, ah[0], al[0]);   // (r,   c..c+1)
        h1pair(x1v, y1v, kb,     sW1a, sW1b, sb1, ah[1], al[1]);   // (r+8, c..c+1)
        h1pair(x0v, y0v, kb + 8, sW1a, sW1b, sb1, ah[2], al[2]);   // (r,   c+8..c+9)
        h1pair(x1v, y1v, kb + 8, sW1a, sW1b, sb1, ah[3], al[3]);   // (r+8, c+8..c+9)

#pragma unroll
        for (int jt = 0; jt < 16; jt++) {
            const int j = jt * 8 + qr;
            const uint32_t* bh = reinterpret_cast<const uint32_t*>(&bthi[j * BTP + kb]);
            uint32_t bh0 = bh[0];
            uint32_t bh1 = *reinterpret_cast<const uint32_t*>(&bthi[j * BTP + kb + 8]);
            mma_bf16(acc[jt], ah, bh0, bh1);   // Ah * Bh
            mma_bf16(acc[jt], al, bh0, bh1);   // Al * Bh
            uint32_t bl0 = *reinterpret_cast<const uint32_t*>(&btlo[j * BTP + kb]);
            uint32_t bl1 = *reinterpret_cast<const uint32_t*>(&btlo[j * BTP + kb + 8]);
            mma_bf16(acc[jt], ah, bl0, bl1);   // Ah * Bl
        }
    }

    // epilogue: h2 = tanh(c + b2); E = sum_j h2*W3 + b3; fx = E^2
    float s0 = 0.0f, s1 = 0.0f;   // rows mr, mr+8
#pragma unroll
    for (int jt = 0; jt < 16; jt++) {
        const int j0 = jt * 8 + qc * 2;
        float b2a = sb2[j0], b2b = sb2[j0 + 1];
        float w3a = sW3[j0], w3b = sW3[j0 + 1];
        s0 = fmaf(tanh_fast(acc[jt][0] + b2a), w3a, s0);
        s0 = fmaf(tanh_fast(acc[jt][1] + b2b), w3b, s0);
        s1 = fmaf(tanh_fast(acc[jt][2] + b2a), w3a, s1);
        s1 = fmaf(tanh_fast(acc[jt][3] + b2b), w3b, s1);
    }
    // quad reduction over qc (lanes differing in bits 0,1)
    s0 += __shfl_xor_sync(0xffffffffu, s0, 1);
    s0 += __shfl_xor_sync(0xffffffffu, s0, 2);
    s1 += __shfl_xor_sync(0xffffffffu, s1, 1);
    s1 += __shfl_xor_sync(0xffffffffu, s1, 2);
    if (qc == 0) {
        float e0 = s0 + sb3;
        float e1 = s1 + sb3;
        g_fx[g0 + mr]     = e0 * e0;
        g_fx[g0 + mr + 8] = e1 * e1;
    }
}

// ---------------- per-row top-100 (exact top_k semantics: value then index) ----------------
__device__ __forceinline__ float block_reduce_512(float v, float* sred) {
    __syncthreads();
    const unsigned mask = 0xffffffffu;
#pragma unroll
    for (int o = 16; o > 0; o >>= 1) v += __shfl_down_sync(mask, v, o);
    int lane = threadIdx.x & 31, wid = threadIdx.x >> 5;
    if (lane == 0) sred[wid] = v;
    __syncthreads();
    if (wid == 0) {
        float r = (lane < 16) ? sred[lane] : 0.0f;
#pragma unroll
        for (int o = 8; o > 0; o >>= 1) r += __shfl_down_sync(mask, r, o);
        if (lane == 0) sred[16] = r;
    }
    __syncthreads();
    return sred[16];
}

__global__ void __launch_bounds__(512) topk_kernel() {
    __shared__ float skey[1024];
    __shared__ float syv[1024];
    __shared__ int   sidx[1024];
    __shared__ float sred[17];
    __shared__ float smu;

    const int tid = threadIdx.x;
    const int b   = blockIdx.x;
    const float* fx = g_fx + (size_t)b * CEM_S;
    const float* yy = g_y  + (size_t)b * CEM_S;

    for (int i = tid; i < 1024; i += 512) {
        if (i < CEM_S) { skey[i] = fx[i]; syv[i] = yy[i]; sidx[i] = i; }
        else           { skey[i] = __int_as_float(0x7f800000); syv[i] = 0.0f; sidx[i] = i; }
    }
    __syncthreads();

    for (int k = 2; k <= 1024; k <<= 1) {
        for (int j = k >> 1; j > 0; j >>= 1) {
            for (int i = tid; i < 1024; i += 512) {
                int l = i ^ j;
                if (l > i) {
                    float ki = skey[i], kl = skey[l];
                    int ii = sidx[i], il = sidx[l];
                    bool gt  = (ki > kl) || (ki == kl && ii > il);
                    bool asc = ((i & k) == 0);
                    if (gt == asc) {
                        skey[i] = kl; skey[l] = ki;
                        sidx[i] = il; sidx[l] = ii;
                        float t = syv[i]; syv[i] = syv[l]; syv[l] = t;
                    }
                }
            }
            __syncthreads();
        }
    }

    float v = (tid < CEM_NE) ? syv[tid] : 0.0f;
    float tot = block_reduce_512(v, sred);
    if (tid == 0) smu = tot / (float)CEM_NE;
    __syncthreads();
    float mu = smu;

    float d  = (tid < CEM_NE) ? (syv[tid] - mu) : 0.0f;
    float ss = block_reduce_512(d * d, sred);
    if (tid == 0) {
        g_mu[b]    = mu;
        g_sigma[b] = sqrtf(ss / (float)CEM_NE);
    }
}

// ---------------- final: yhat + diag-Gaussian samples ----------------
__global__ void sample_kernel(uint32_t k0, uint32_t k1, float* __restrict__ out) {
    int gid = blockIdx.x * blockDim.x + threadIdx.x;
    if (gid >= TOTAL) return;
    int b = gid & (NBATCH - 1);
    float eps = bits_to_normal(tf_bits32(k0, k1, (uint32_t)gid));
    float mu = g_mu[b], sg = g_sigma[b];
    float cov = sg * sg;
    cov = fminf(fmaxf(cov, 1e-3f), 100.0f);
    out[NBATCH + gid] = mu + sqrtf(cov) * eps;
    if (gid < NBATCH) out[gid] = g_mu[gid];
}

// ---------------- launch ----------------
extern "C" void kernel_launch(void* const* d_in, const int* in_sizes, int n_in,
                              void* d_out, int out_size)
{
    const float* x  = (const float*)d_in[0];
    const float* W1 = (const float*)d_in[1];
    const float* b1 = (const float*)d_in[2];
    const float* W2 = (const float*)d_in[3];
    const float* b2 = (const float*)d_in[4];
    const float* W3 = (const float*)d_in[5];
    const float* b3 = (const float*)d_in[6];
    float* out = (float*)d_out;

    // JAX partitionable-mode key derivation
    uint32_t cem0 = 0u, cem1 = 0u; threefry2x32(0u, 42u, cem0, cem1);   // split(key,2)[0]
    uint32_t smp0 = 0u, smp1 = 1u; threefry2x32(0u, 42u, smp0, smp1);   // split(key,2)[1]

    uint32_t ik0[CEM_NI], ik1[CEM_NI];
    for (int i = 0; i < CEM_NI; i++) {
        uint32_t a = 0u, c = (uint32_t)i;
        threefry2x32(cem0, cem1, a, c);
        ik0[i] = a; ik1[i] = c;
    }

    const int SMEM_BYTES = 2 * HID * BTP * (int)sizeof(uint16_t);   // 69,632 B
    cudaFuncSetAttribute(energy_kernel, cudaFuncAttributeMaxDynamicSharedMemorySize, SMEM_BYTES);

    w2prep_kernel<<<(HID * HID + 255) / 256, 256>>>(W2);
    init_kernel<<<(NBATCH + 255) / 256, 256>>>();

    for (int i = 0; i < CEM_NI; i++) {
        energy_kernel<<<TOTAL / 128, 256, SMEM_BYTES>>>(ik0[i], ik1[i], x, W1, b1, b2, W3, b3);
        topk_kernel<<<NBATCH, 512>>>();
    }

    sample_kernel<<<(TOTAL + 255) / 256, 256>>>(smp0, smp1, out);
}

// round 11
// speedup vs baseline: 3.1392x; 1.2247x over previous
#include <cuda_runtime.h>
#include <cuda_bf16.h>
#include <cstdint>

#define NBATCH   2048
#define CEM_S    1000
#define CEM_NE   100
#define CEM_NI   10
#define HID      128
#define BTP      136                  // padded k-row length for B^T tiles (bank-spread)
#define TOTAL    (NBATCH * CEM_S)     // 2,048,000
#define INIT_SIG 10.0f

// ---------------- device scratch (no allocations allowed) ----------------
__device__ float g_mu[NBATCH];
__device__ float g_sigma[NBATCH];
__device__ float g_y[TOTAL];
__device__ float g_fx[TOTAL];
// W2^T split into bf16 hi/lo: [j][k] with row pad BTP
__device__ __align__(16) uint16_t g_BThi[HID * BTP];
__device__ __align__(16) uint16_t g_BTlo[HID * BTP];

// ---------------- threefry-2x32 (exact JAX, partitionable mode) ----------------
static __host__ __device__ __forceinline__ uint32_t rotl32(uint32_t v, uint32_t d) {
    return (v << d) | (v >> (32u - d));
}

static __host__ __device__ __forceinline__ void threefry2x32(
    uint32_t k0, uint32_t k1, uint32_t& x0, uint32_t& x1)
{
    uint32_t ks0 = k0, ks1 = k1, ks2 = k0 ^ k1 ^ 0x1BD11BDAu;
    x0 += ks0; x1 += ks1;
#define TF_R(r) { x0 += x1; x1 = rotl32(x1, r); x1 ^= x0; }
    TF_R(13) TF_R(15) TF_R(26) TF_R(6)   x0 += ks1; x1 += ks2 + 1u;
    TF_R(17) TF_R(29) TF_R(16) TF_R(24)  x0 += ks2; x1 += ks0 + 2u;
    TF_R(13) TF_R(15) TF_R(26) TF_R(6)   x0 += ks0; x1 += ks1 + 3u;
    TF_R(17) TF_R(29) TF_R(16) TF_R(24)  x0 += ks1; x1 += ks2 + 4u;
    TF_R(13) TF_R(15) TF_R(26) TF_R(6)   x0 += ks2; x1 += ks0 + 5u;
#undef TF_R
}

__device__ __forceinline__ uint32_t tf_bits32(uint32_t k0, uint32_t k1, uint32_t idx) {
    uint32_t x0 = 0u, x1 = idx;
    threefry2x32(k0, k1, x0, x1);
    return x0 ^ x1;
}

__device__ __forceinline__ float bits_to_normal(uint32_t bits) {
    float f = __uint_as_float((bits >> 9) | 0x3f800000u) - 1.0f;   // [0,1)
    const float lo = -0.99999994f;
    float u = fmaxf(lo, f * 2.0f + lo);
    float w = -log1pf(-u * u);
    float p;
    if (w < 5.0f) {
        w -= 2.5f;
        p = 2.81022636e-08f;
        p = fmaf(p, w, 3.43273939e-07f);
        p = fmaf(p, w, -3.5233877e-06f);
        p = fmaf(p, w, -4.39150654e-06f);
        p = fmaf(p, w, 0.00021858087f);
        p = fmaf(p, w, -0.00125372503f);
        p = fmaf(p, w, -0.00417768164f);
        p = fmaf(p, w, 0.246640727f);
        p = fmaf(p, w, 1.50140941f);
    } else {
        w = sqrtf(w) - 3.0f;
        p = -0.000200214257f;
        p = fmaf(p, w, 0.000100950558f);
        p = fmaf(p, w, 0.00134934322f);
        p = fmaf(p, w, -0.00367342844f);
        p = fmaf(p, w, 0.00573950773f);
        p = fmaf(p, w, -0.0076224613f);
        p = fmaf(p, w, 0.00943887047f);
        p = fmaf(p, w, 1.00167406f);
        p = fmaf(p, w, 2.83297682f);
    }
    return 1.4142135623730951f * (p * u);
}

// ---------------- fast tanh: 1 - 2/(e^{2x}+1), MUFU ex2 + rcp ----------------
__device__ __forceinline__ float tanh_fast(float x) {
    float m = x * 2.8853900817779268f;   // 2 * log2(e)
    float e;
    asm("ex2.approx.f32 %0, %1;" : "=f"(e) : "f"(m));
    float den = e + 1.0f;
    float r;
    asm("rcp.approx.f32 %0, %1;" : "=f"(r) : "f"(den));
    return fmaf(-2.0f, r, 1.0f);
}

// ---------------- bf16 mma helper ----------------
__device__ __forceinline__ void mma_bf16(float* d, const uint32_t* a, uint32_t b0, uint32_t b1) {
    asm volatile(
        "mma.sync.aligned.m16n8k16.row.col.f32.bf16.bf16.f32 "
        "{%0,%1,%2,%3}, {%4,%5,%6,%7}, {%8,%9}, {%0,%1,%2,%3};"
        : "+f"(d[0]), "+f"(d[1]), "+f"(d[2]), "+f"(d[3])
        : "r"(a[0]), "r"(a[1]), "r"(a[2]), "r"(a[3]), "r"(b0), "r"(b1));
}

// compute h1 for (x,y) at k and k+1; emit packed bf16 hi-pair and lo-pair
__device__ __forceinline__ void h1pair(
    float x, float y, int k,
    const float* sW1a, const float* sW1b, const float* sb1,
    uint32_t& ah, uint32_t& al)
{
    float v0 = tanh_fast(fmaf(x, sW1a[k],     fmaf(y, sW1b[k],     sb1[k])));
    float v1 = tanh_fast(fmaf(x, sW1a[k + 1], fmaf(y, sW1b[k + 1], sb1[k + 1])));
    __nv_bfloat16 h0 = __float2bfloat16(v0);
    __nv_bfloat16 h1 = __float2bfloat16(v1);
    __nv_bfloat16 l0 = __float2bfloat16(v0 - __bfloat162float(h0));
    __nv_bfloat16 l1 = __float2bfloat16(v1 - __bfloat162float(h1));
    ah = (uint32_t)__bfloat16_as_ushort(h0) | ((uint32_t)__bfloat16_as_ushort(h1) << 16);
    al = (uint32_t)__bfloat16_as_ushort(l0) | ((uint32_t)__bfloat16_as_ushort(l1) << 16);
}

// ---------------- prep: W2 -> bf16 hi/lo transposed padded images ----------------
__global__ void w2prep_kernel(const float* __restrict__ W2) {
    int i = blockIdx.x * blockDim.x + threadIdx.x;   // i = k*128 + j
    if (i >= HID * HID) return;
    int k = i >> 7, j = i & 127;
    float v = W2[i];
    __nv_bfloat16 hb = __float2bfloat16(v);
    __nv_bfloat16 lb = __float2bfloat16(v - __bfloat162float(hb));
    g_BThi[j * BTP + k] = __bfloat16_as_ushort(hb);
    g_BTlo[j * BTP + k] = __bfloat16_as_ushort(lb);
}

// ---------------- init ----------------
__global__ void init_kernel() {
    int i = blockIdx.x * blockDim.x + threadIdx.x;
    if (i < NBATCH) { g_mu[i] = 0.0f; g_sigma[i] = INIT_SIG; }
}

// ---------------- fused sample + energy kernel (mma.sync bf16 3-term split) ----------------
// One block = 128 candidates. 256 threads (8 warps), 2 CTAs/SM.
// Warp w computes rows m in [16w, 16w+16) x all 128 j. A fragments are computed
// in registers (tanh + split, zero smem); B^T hi/lo tiles staged once per CTA.
__global__ void __launch_bounds__(256, 2) energy_kernel(
    uint32_t k0, uint32_t k1,
    const float* __restrict__ x,  const float* __restrict__ W1, const float* __restrict__ b1,
    const float* __restrict__ b2, const float* __restrict__ W3, const float* __restrict__ b3)
{
    extern __shared__ uint16_t btile[];
    uint16_t* bthi = btile;                  // [128 * BTP]
    uint16_t* btlo = btile + HID * BTP;      // [128 * BTP]

    __shared__ float sy[128], sxv[128];
    __shared__ float sW1a[HID], sW1b[HID], sb1[HID], sb2[HID], sW3[HID];
    __shared__ float sb3;

    const int tid  = threadIdx.x;
    const int w    = tid >> 5;
    const int lane = tid & 31;
    const int g0   = blockIdx.x * 128;

    // stage B^T hi/lo images (linear uint4 copy; 2176 uint4 each)
    {
        const uint4* gh = reinterpret_cast<const uint4*>(g_BThi);
        const uint4* gl = reinterpret_cast<const uint4*>(g_BTlo);
        uint4* sh = reinterpret_cast<uint4*>(bthi);
        uint4* sl = reinterpret_cast<uint4*>(btlo);
#pragma unroll
        for (int i = tid; i < HID * BTP / 8; i += 256) { sh[i] = gh[i]; sl[i] = gl[i]; }
    }

    // stage small weights
    if (tid < HID) {
        sW1a[tid] = W1[tid];
        sW1b[tid] = W1[HID + tid];
        sb1[tid]  = b1[tid];
        sb2[tid]  = b2[tid];
        sW3[tid]  = W3[tid];
    }
    if (tid == 0) sb3 = b3[0];

    // candidates: eps via threefry (partitionable), Ys = mu + sigma*eps
    if (tid < 128) {
        int g = g0 + tid;
        int b = g / CEM_S;
        float eps = bits_to_normal(tf_bits32(k0, k1, (uint32_t)g));
        float yv  = g_mu[b] + g_sigma[b] * eps;
        sy[tid]  = yv;
        sxv[tid] = x[b];
        g_y[g]   = yv;
    }
    __syncthreads();

    // fragment coordinates
    const int qr = lane >> 2;       // 0..7 : row-in-tile / B column selector
    const int qc = lane & 3;        // 0..3 : k-pair selector
    const int mr = 16 * w + qr;     // rows mr, mr+8
    const float x0v = sxv[mr],     y0v = sy[mr];
    const float x1v = sxv[mr + 8], y1v = sy[mr + 8];

    float acc[16][4];
#pragma unroll
    for (int jt = 0; jt < 16; jt++)
#pragma unroll
        for (int c = 0; c < 4; c++) acc[jt][c] = 0.0f;

#pragma unroll
    for (int s = 0; s < 8; s++) {
        const int kb = 16 * s + qc * 2;

        // A fragments (hi & lo), computed in registers
        uint32_t ah[4], al[4];
        h1pair(x0v, y0v, kb,     sW1a, sW1b, sb1, ah[0], al[0]);   // (r,   c..c+1)
        h1pair(x1v, y1v, kb,     sW1a, sW1b, sb1, ah[1], al[1]);   // (r+8, c..c+1)
        h1pair(x0v, y0v, kb + 8, sW1a, sW1b, sb1, ah[2], al[2]);   // (r,   c+8..c+9)
        h1pair(x1v, y1v, kb + 8, sW1a, sW1b, sb1, ah[3], al[3]);   // (r+8, c+8..c+9)

#pragma unroll
        for (int jt = 0; jt < 16; jt++) {
            const int j = jt * 8 + qr;
            const uint32_t* bh = reinterpret_cast<const uint32_t*>(&bthi[j * BTP + kb]);
            uint32_t bh0 = bh[0];
            uint32_t bh1 = *reinterpret_cast<const uint32_t*>(&bthi[j * BTP + kb + 8]);
            mma_bf16(acc[jt], ah, bh0, bh1);   // Ah * Bh
            mma_bf16(acc[jt], al, bh0, bh1);   // Al * Bh
            uint32_t bl0 = *reinterpret_cast<const uint32_t*>(&btlo[j * BTP + kb]);
            uint32_t bl1 = *reinterpret_cast<const uint32_t*>(&btlo[j * BTP + kb + 8]);
            mma_bf16(acc[jt], ah, bl0, bl1);   // Ah * Bl
        }
    }

    // epilogue: h2 = tanh(c + b2); E = sum_j h2*W3 + b3; fx = E^2
    float s0 = 0.0f, s1 = 0.0f;   // rows mr, mr+8
#pragma unroll
    for (int jt = 0; jt < 16; jt++) {
        const int j0 = jt * 8 + qc * 2;
        float b2a = sb2[j0], b2b = sb2[j0 + 1];
        float w3a = sW3[j0], w3b = sW3[j0 + 1];
        s0 = fmaf(tanh_fast(acc[jt][0] + b2a), w3a, s0);
        s0 = fmaf(tanh_fast(acc[jt][1] + b2b), w3b, s0);
        s1 = fmaf(tanh_fast(acc[jt][2] + b2a), w3a, s1);
        s1 = fmaf(tanh_fast(acc[jt][3] + b2b), w3b, s1);
    }
    // quad reduction over qc (lanes differing in bits 0,1)
    s0 += __shfl_xor_sync(0xffffffffu, s0, 1);
    s0 += __shfl_xor_sync(0xffffffffu, s0, 2);
    s1 += __shfl_xor_sync(0xffffffffu, s1, 1);
    s1 += __shfl_xor_sync(0xffffffffu, s1, 2);
    if (qc == 0) {
        float e0 = s0 + sb3;
        float e1 = s1 + sb3;
        g_fx[g0 + mr]     = e0 * e0;
        g_fx[g0 + mr + 8] = e1 * e1;
    }
}

// ---------------- per-row top-100 via MSB radix-select (exact top_k semantics) ----------------
// fx >= 0, so uint bit pattern preserves order. 256 threads; thread t owns the 4
// CONTIGUOUS indices [4t, 4t+4) -> index-order tie-break falls out of a prefix scan.
__device__ __forceinline__ float block_reduce_256(float v, float* sred) {
    __syncthreads();
    const unsigned mask = 0xffffffffu;
#pragma unroll
    for (int o = 16; o > 0; o >>= 1) v += __shfl_down_sync(mask, v, o);
    int lane = threadIdx.x & 31, w = threadIdx.x >> 5;
    if (lane == 0) sred[w] = v;
    __syncthreads();
    if (w == 0) {
        float r = (lane < 8) ? sred[lane] : 0.0f;
#pragma unroll
        for (int o = 4; o > 0; o >>= 1) r += __shfl_down_sync(mask, r, o);
        if (lane == 0) sred[8] = r;
    }
    __syncthreads();
    return sred[8];
}

__global__ void __launch_bounds__(256) topk_kernel() {
    __shared__ unsigned int sc[256];
    __shared__ unsigned int sh_dig, sh_below;
    __shared__ float sredf[9];
    __shared__ float smu;

    const int tid = threadIdx.x;
    const int b   = blockIdx.x;
    const float* fx = g_fx + (size_t)b * CEM_S;
    const float* yy = g_y  + (size_t)b * CEM_S;

    unsigned int uk[4];
    float yv[4];
    const int i0 = tid * 4;
#pragma unroll
    for (int e = 0; e < 4; e++) {
        int i = i0 + e;
        if (i < CEM_S) { uk[e] = __float_as_uint(fx[i]); yv[e] = yy[i]; }
        else           { uk[e] = 0xFFFFFFFFu; yv[e] = 0.0f; }   // padding > any finite key
    }

    unsigned int pref = 0;     // high bits of the K-th smallest key found so far
    int kRem = CEM_NE;

#pragma unroll
    for (int p = 24; p >= 0; p -= 8) {
        sc[tid] = 0u;
        __syncthreads();
#pragma unroll
        for (int e = 0; e < 4; e++) {
            bool act = (p == 24) || ((uk[e] >> (p + 8)) == pref);
            if (act) atomicAdd(&sc[(uk[e] >> p) & 0xFFu], 1u);
        }
        __syncthreads();
        // inclusive scan of 256 bins (Hillis-Steele)
        for (int off = 1; off < 256; off <<= 1) {
            unsigned int add = (tid >= off) ? sc[tid - off] : 0u;
            __syncthreads();
            sc[tid] += add;
            __syncthreads();
        }
        unsigned int cum  = sc[tid];
        unsigned int prev = (tid == 0) ? 0u : sc[tid - 1];
        if (cum >= (unsigned)kRem && prev < (unsigned)kRem) { sh_dig = (unsigned)tid; sh_below = prev; }
        __syncthreads();
        pref = (pref << 8) | sh_dig;
        kRem -= (int)sh_below;
        __syncthreads();
    }
    const unsigned int T = pref;   // exact key value of the 100th smallest
    const int r = kRem;            // how many ==T to take (smallest indices first)

    // exclusive prefix of per-thread equal counts (contiguous index ownership)
    unsigned int eqc = 0;
#pragma unroll
    for (int e = 0; e < 4; e++) eqc += (uk[e] == T);
    sc[tid] = eqc;
    __syncthreads();
    for (int off = 1; off < 256; off <<= 1) {
        unsigned int add = (tid >= off) ? sc[tid - off] : 0u;
        __syncthreads();
        sc[tid] += add;
        __syncthreads();
    }
    const unsigned int baseEq = sc[tid] - eqc;

    // elite sum -> mu
    float sum = 0.0f;
    {
        unsigned int o = 0;
#pragma unroll
        for (int e = 0; e < 4; e++) {
            bool isEq = (uk[e] == T);
            bool sel  = (uk[e] < T) || (isEq && (baseEq + o) < (unsigned)r);
            if (isEq) o++;
            if (sel) sum += yv[e];
        }
    }
    float tot = block_reduce_256(sum, sredf);
    if (tid == 0) smu = tot / (float)CEM_NE;
    __syncthreads();
    const float mu = smu;

    // elite variance -> sigma
    float ss = 0.0f;
    {
        unsigned int o = 0;
#pragma unroll
        for (int e = 0; e < 4; e++) {
            bool isEq = (uk[e] == T);
            bool sel  = (uk[e] < T) || (isEq && (baseEq + o) < (unsigned)r);
            if (isEq) o++;
            if (sel) { float d = yv[e] - mu; ss = fmaf(d, d, ss); }
        }
    }
    float sst = block_reduce_256(ss, sredf);
    if (tid == 0) {
        g_mu[b]    = mu;
        g_sigma[b] = sqrtf(sst / (float)CEM_NE);
    }
}

// ---------------- final: yhat + diag-Gaussian samples ----------------
__global__ void sample_kernel(uint32_t k0, uint32_t k1, float* __restrict__ out) {
    int gid = blockIdx.x * blockDim.x + threadIdx.x;
    if (gid >= TOTAL) return;
    int b = gid & (NBATCH - 1);
    float eps = bits_to_normal(tf_bits32(k0, k1, (uint32_t)gid));
    float mu = g_mu[b], sg = g_sigma[b];
    float cov = sg * sg;
    cov = fminf(fmaxf(cov, 1e-3f), 100.0f);
    out[NBATCH + gid] = mu + sqrtf(cov) * eps;
    if (gid < NBATCH) out[gid] = g_mu[gid];
}

// ---------------- launch ----------------
extern "C" void kernel_launch(void* const* d_in, const int* in_sizes, int n_in,
                              void* d_out, int out_size)
{
    const float* x  = (const float*)d_in[0];
    const float* W1 = (const float*)d_in[1];
    const float* b1 = (const float*)d_in[2];
    const float* W2 = (const float*)d_in[3];
    const float* b2 = (const float*)d_in[4];
    const float* W3 = (const float*)d_in[5];
    const float* b3 = (const float*)d_in[6];
    float* out = (float*)d_out;

    // JAX partitionable-mode key derivation
    uint32_t cem0 = 0u, cem1 = 0u; threefry2x32(0u, 42u, cem0, cem1);   // split(key,2)[0]
    uint32_t smp0 = 0u, smp1 = 1u; threefry2x32(0u, 42u, smp0, smp1);   // split(key,2)[1]

    uint32_t ik0[CEM_NI], ik1[CEM_NI];
    for (int i = 0; i < CEM_NI; i++) {
        uint32_t a = 0u, c = (uint32_t)i;
        threefry2x32(cem0, cem1, a, c);
        ik0[i] = a; ik1[i] = c;
    }

    const int SMEM_BYTES = 2 * HID * BTP * (int)sizeof(uint16_t);   // 69,632 B
    cudaFuncSetAttribute(energy_kernel, cudaFuncAttributeMaxDynamicSharedMemorySize, SMEM_BYTES);

    w2prep_kernel<<<(HID * HID + 255) / 256, 256>>>(W2);
    init_kernel<<<(NBATCH + 255) / 256, 256>>>();

    for (int i = 0; i < CEM_NI; i++) {
        energy_kernel<<<TOTAL / 128, 256, SMEM_BYTES>>>(ik0[i], ik1[i], x, W1, b1, b2, W3, b3);
        topk_kernel<<<NBATCH, 256>>>();
    }

    sample_kernel<<<(TOTAL + 255) / 256, 256>>>(smp0, smp1, out);
}

// round 12
// speedup vs baseline: 3.2650x; 1.0401x over previous
#include <cuda_runtime.h>
#include <cuda_bf16.h>
#include <cstdint>

#define NBATCH   2048
#define CEM_S    1000
#define CEM_NE   100
#define CEM_NI   10
#define HID      128
#define TOTAL    (NBATCH * CEM_S)     // 2,048,000
#define INIT_SIG 10.0f

// ---------------- device scratch (no allocations allowed) ----------------
__device__ float g_mu[NBATCH];
__device__ float g_sigma[NBATCH];
__device__ float g_y[TOTAL];
__device__ float g_fx[TOTAL];
// W2 in mma-fragment order: [s:8][jt:16][lane:32] -> (bh0, bh1, bl0, bl1)
__device__ __align__(16) uint4 g_Bfrag[8 * 16 * 32];

// ---------------- threefry-2x32 (exact JAX, partitionable mode) ----------------
static __host__ __device__ __forceinline__ uint32_t rotl32(uint32_t v, uint32_t d) {
    return (v << d) | (v >> (32u - d));
}

static __host__ __device__ __forceinline__ void threefry2x32(
    uint32_t k0, uint32_t k1, uint32_t& x0, uint32_t& x1)
{
    uint32_t ks0 = k0, ks1 = k1, ks2 = k0 ^ k1 ^ 0x1BD11BDAu;
    x0 += ks0; x1 += ks1;
#define TF_R(r) { x0 += x1; x1 = rotl32(x1, r); x1 ^= x0; }
    TF_R(13) TF_R(15) TF_R(26) TF_R(6)   x0 += ks1; x1 += ks2 + 1u;
    TF_R(17) TF_R(29) TF_R(16) TF_R(24)  x0 += ks2; x1 += ks0 + 2u;
    TF_R(13) TF_R(15) TF_R(26) TF_R(6)   x0 += ks0; x1 += ks1 + 3u;
    TF_R(17) TF_R(29) TF_R(16) TF_R(24)  x0 += ks1; x1 += ks2 + 4u;
    TF_R(13) TF_R(15) TF_R(26) TF_R(6)   x0 += ks2; x1 += ks0 + 5u;
#undef TF_R
}

__device__ __forceinline__ uint32_t tf_bits32(uint32_t k0, uint32_t k1, uint32_t idx) {
    uint32_t x0 = 0u, x1 = idx;
    threefry2x32(k0, k1, x0, x1);
    return x0 ^ x1;
}

__device__ __forceinline__ float bits_to_normal(uint32_t bits) {
    float f = __uint_as_float((bits >> 9) | 0x3f800000u) - 1.0f;   // [0,1)
    const float lo = -0.99999994f;
    float u = fmaxf(lo, f * 2.0f + lo);
    float w = -log1pf(-u * u);
    float p;
    if (w < 5.0f) {
        w -= 2.5f;
        p = 2.81022636e-08f;
        p = fmaf(p, w, 3.43273939e-07f);
        p = fmaf(p, w, -3.5233877e-06f);
        p = fmaf(p, w, -4.39150654e-06f);
        p = fmaf(p, w, 0.00021858087f);
        p = fmaf(p, w, -0.00125372503f);
        p = fmaf(p, w, -0.00417768164f);
        p = fmaf(p, w, 0.246640727f);
        p = fmaf(p, w, 1.50140941f);
    } else {
        w = sqrtf(w) - 3.0f;
        p = -0.000200214257f;
        p = fmaf(p, w, 0.000100950558f);
        p = fmaf(p, w, 0.00134934322f);
        p = fmaf(p, w, -0.00367342844f);
        p = fmaf(p, w, 0.00573950773f);
        p = fmaf(p, w, -0.0076224613f);
        p = fmaf(p, w, 0.00943887047f);
        p = fmaf(p, w, 1.00167406f);
        p = fmaf(p, w, 2.83297682f);
    }
    return 1.4142135623730951f * (p * u);
}

// ---------------- fast tanh: 1 - 2/(e^{2x}+1), MUFU ex2 + rcp ----------------
__device__ __forceinline__ float tanh_fast(float x) {
    float m = x * 2.8853900817779268f;   // 2 * log2(e)
    float e;
    asm("ex2.approx.f32 %0, %1;" : "=f"(e) : "f"(m));
    float den = e + 1.0f;
    float r;
    asm("rcp.approx.f32 %0, %1;" : "=f"(r) : "f"(den));
    return fmaf(-2.0f, r, 1.0f);
}

// ---------------- bf16 mma helper ----------------
__device__ __forceinline__ void mma_bf16(float* d, const uint32_t* a, uint32_t b0, uint32_t b1) {
    asm volatile(
        "mma.sync.aligned.m16n8k16.row.col.f32.bf16.bf16.f32 "
        "{%0,%1,%2,%3}, {%4,%5,%6,%7}, {%8,%9}, {%0,%1,%2,%3};"
        : "+f"(d[0]), "+f"(d[1]), "+f"(d[2]), "+f"(d[3])
        : "r"(a[0]), "r"(a[1]), "r"(a[2]), "r"(a[3]), "r"(b0), "r"(b1));
}

// compute h1 at k and k+1; emit packed bf16 hi-pair (lo half = k) and lo-pair.
// cvt.rn.bf16x2.f32 d,a,b : d.hi=cvt(a), d.lo=cvt(b) -- .rn matches __float2bfloat16.
__device__ __forceinline__ void h1pair(
    float x, float y, int k,
    const float* sW1a, const float* sW1b, const float* sb1,
    uint32_t& ah, uint32_t& al)
{
    float v0 = tanh_fast(fmaf(x, sW1a[k],     fmaf(y, sW1b[k],     sb1[k])));
    float v1 = tanh_fast(fmaf(x, sW1a[k + 1], fmaf(y, sW1b[k + 1], sb1[k + 1])));
    asm("cvt.rn.bf16x2.f32 %0, %1, %2;" : "=r"(ah) : "f"(v1), "f"(v0));
    float h0 = __uint_as_float(ah << 16);
    float h1 = __uint_as_float(ah & 0xFFFF0000u);
    float l0 = v0 - h0;
    float l1 = v1 - h1;
    asm("cvt.rn.bf16x2.f32 %0, %1, %2;" : "=r"(al) : "f"(l1), "f"(l0));
}

// ---------------- prep: W2 -> fragment-ordered hi/lo uint4 image ----------------
// thread i -> (s, jt, lane): lane=(qr,qc); j = jt*8+qr; kb = 16s + 2qc.
// bh0 = hi(W2[kb][j], W2[kb+1][j]); bh1 = hi(k+8); bl0/bl1 = lo parts.
__global__ void w2prep_kernel(const float* __restrict__ W2) {
    int i = blockIdx.x * blockDim.x + threadIdx.x;
    if (i >= 8 * 16 * 32) return;
    int lane = i & 31, jt = (i >> 5) & 15, s = i >> 9;
    int qr = lane >> 2, qc = lane & 3;
    int j  = jt * 8 + qr;
    int kb = s * 16 + qc * 2;

    float v[4] = { W2[kb * 128 + j],       W2[(kb + 1) * 128 + j],
                   W2[(kb + 8) * 128 + j], W2[(kb + 9) * 128 + j] };
    uint32_t hw[4], lw[4];
#pragma unroll
    for (int t = 0; t < 4; t++) {
        __nv_bfloat16 hb = __float2bfloat16(v[t]);
        __nv_bfloat16 lb = __float2bfloat16(v[t] - __bfloat162float(hb));
        hw[t] = (uint32_t)__bfloat16_as_ushort(hb);
        lw[t] = (uint32_t)__bfloat16_as_ushort(lb);
    }
    uint4 f;
    f.x = hw[0] | (hw[1] << 16);   // bh0 : k = kb, kb+1
    f.y = hw[2] | (hw[3] << 16);   // bh1 : k = kb+8, kb+9
    f.z = lw[0] | (lw[1] << 16);   // bl0
    f.w = lw[2] | (lw[3] << 16);   // bl1
    g_Bfrag[i] = f;
}

// ---------------- init ----------------
__global__ void init_kernel() {
    int i = blockIdx.x * blockDim.x + threadIdx.x;
    if (i < NBATCH) { g_mu[i] = 0.0f; g_sigma[i] = INIT_SIG; }
}

// ---------------- fused sample + energy kernel (mma.sync bf16 3-term split) ----------------
// One block = 128 candidates. 256 threads (8 warps), 2 CTAs/SM.
// B fragments pre-packed per lane: 1 LDS.128 per (s, jt) replaces 4 LDS.32.
__global__ void __launch_bounds__(256, 2) energy_kernel(
    uint32_t k0, uint32_t k1,
    const float* __restrict__ x,  const float* __restrict__ W1, const float* __restrict__ b1,
    const float* __restrict__ b2, const float* __restrict__ W3, const float* __restrict__ b3)
{
    extern __shared__ uint4 bfrag[];     // [8*16*32] = 64KB

    __shared__ float sy[128], sxv[128];
    __shared__ float sW1a[HID], sW1b[HID], sb1[HID], sb2[HID], sW3[HID];
    __shared__ float sb3;

    const int tid  = threadIdx.x;
    const int w    = tid >> 5;
    const int lane = tid & 31;
    const int g0   = blockIdx.x * 128;

    // stage fragment image (linear uint4 copy, 4096 entries)
#pragma unroll
    for (int i = tid; i < 8 * 16 * 32; i += 256) bfrag[i] = g_Bfrag[i];

    // stage small weights
    if (tid < HID) {
        sW1a[tid] = W1[tid];
        sW1b[tid] = W1[HID + tid];
        sb1[tid]  = b1[tid];
        sb2[tid]  = b2[tid];
        sW3[tid]  = W3[tid];
    }
    if (tid == 0) sb3 = b3[0];

    // candidates: eps via threefry (partitionable), Ys = mu + sigma*eps
    if (tid < 128) {
        int g = g0 + tid;
        int b = g / CEM_S;
        float eps = bits_to_normal(tf_bits32(k0, k1, (uint32_t)g));
        float yv  = g_mu[b] + g_sigma[b] * eps;
        sy[tid]  = yv;
        sxv[tid] = x[b];
        g_y[g]   = yv;
    }
    __syncthreads();

    // fragment coordinates
    const int qr = lane >> 2;       // 0..7
    const int qc = lane & 3;        // 0..3
    const int mr = 16 * w + qr;     // rows mr, mr+8
    const float x0v = sxv[mr],     y0v = sy[mr];
    const float x1v = sxv[mr + 8], y1v = sy[mr + 8];

    float acc[16][4];
#pragma unroll
    for (int jt = 0; jt < 16; jt++)
#pragma unroll
        for (int c = 0; c < 4; c++) acc[jt][c] = 0.0f;

#pragma unroll
    for (int s = 0; s < 8; s++) {
        const int kb = 16 * s + qc * 2;

        // A fragments (hi & lo), computed in registers
        uint32_t ah[4], al[4];
        h1pair(x0v, y0v, kb,     sW1a, sW1b, sb1, ah[0], al[0]);   // (r,   c..c+1)
        h1pair(x1v, y1v, kb,     sW1a, sW1b, sb1, ah[1], al[1]);   // (r+8, c..c+1)
        h1pair(x0v, y0v, kb + 8, sW1a, sW1b, sb1, ah[2], al[2]);   // (r,   c+8..c+9)
        h1pair(x1v, y1v, kb + 8, sW1a, sW1b, sb1, ah[3], al[3]);   // (r+8, c+8..c+9)

        const uint4* srow = bfrag + (s << 9) + lane;   // [s][jt][lane]
#pragma unroll
        for (int jt = 0; jt < 16; jt++) {
            uint4 f = srow[jt << 5];
            mma_bf16(acc[jt], ah, f.x, f.y);   // Ah * Bh
            mma_bf16(acc[jt], al, f.x, f.y);   // Al * Bh
            mma_bf16(acc[jt], ah, f.z, f.w);   // Ah * Bl
        }
    }

    // epilogue: h2 = tanh(c + b2); E = sum_j h2*W3 + b3; fx = E^2
    float s0 = 0.0f, s1 = 0.0f;   // rows mr, mr+8
#pragma unroll
    for (int jt = 0; jt < 16; jt++) {
        const int j0 = jt * 8 + qc * 2;
        float b2a = sb2[j0], b2b = sb2[j0 + 1];
        float w3a = sW3[j0], w3b = sW3[j0 + 1];
        s0 = fmaf(tanh_fast(acc[jt][0] + b2a), w3a, s0);
        s0 = fmaf(tanh_fast(acc[jt][1] + b2b), w3b, s0);
        s1 = fmaf(tanh_fast(acc[jt][2] + b2a), w3a, s1);
        s1 = fmaf(tanh_fast(acc[jt][3] + b2b), w3b, s1);
    }
    // quad reduction over qc (lanes differing in bits 0,1)
    s0 += __shfl_xor_sync(0xffffffffu, s0, 1);
    s0 += __shfl_xor_sync(0xffffffffu, s0, 2);
    s1 += __shfl_xor_sync(0xffffffffu, s1, 1);
    s1 += __shfl_xor_sync(0xffffffffu, s1, 2);
    if (qc == 0) {
        float e0 = s0 + sb3;
        float e1 = s1 + sb3;
        g_fx[g0 + mr]     = e0 * e0;
        g_fx[g0 + mr + 8] = e1 * e1;
    }
}

// ---------------- per-row top-100 via MSB radix-select (exact top_k semantics) ----------------
__device__ __forceinline__ float block_reduce_256(float v, float* sred) {
    __syncthreads();
    const unsigned mask = 0xffffffffu;
#pragma unroll
    for (int o = 16; o > 0; o >>= 1) v += __shfl_down_sync(mask, v, o);
    int lane = threadIdx.x & 31, w = threadIdx.x >> 5;
    if (lane == 0) sred[w] = v;
    __syncthreads();
    if (w == 0) {
        float r = (lane < 8) ? sred[lane] : 0.0f;
#pragma unroll
        for (int o = 4; o > 0; o >>= 1) r += __shfl_down_sync(mask, r, o);
        if (lane == 0) sred[8] = r;
    }
    __syncthreads();
    return sred[8];
}

__global__ void __launch_bounds__(256) topk_kernel() {
    __shared__ unsigned int sc[256];
    __shared__ unsigned int sh_dig, sh_below;
    __shared__ float sredf[9];
    __shared__ float smu;

    const int tid = threadIdx.x;
    const int b   = blockIdx.x;
    const float* fx = g_fx + (size_t)b * CEM_S;
    const float* yy = g_y  + (size_t)b * CEM_S;

    unsigned int uk[4];
    float yv[4];
    const int i0 = tid * 4;
#pragma unroll
    for (int e = 0; e < 4; e++) {
        int i = i0 + e;
        if (i < CEM_S) { uk[e] = __float_as_uint(fx[i]); yv[e] = yy[i]; }
        else           { uk[e] = 0xFFFFFFFFu; yv[e] = 0.0f; }   // padding > any finite key
    }

    unsigned int pref = 0;
    int kRem = CEM_NE;

#pragma unroll
    for (int p = 24; p >= 0; p -= 8) {
        sc[tid] = 0u;
        __syncthreads();
#pragma unroll
        for (int e = 0; e < 4; e++) {
            bool act = (p == 24) || ((uk[e] >> (p + 8)) == pref);
            if (act) atomicAdd(&sc[(uk[e] >> p) & 0xFFu], 1u);
        }
        __syncthreads();
        for (int off = 1; off < 256; off <<= 1) {
            unsigned int add = (tid >= off) ? sc[tid - off] : 0u;
            __syncthreads();
            sc[tid] += add;
            __syncthreads();
        }
        unsigned int cum  = sc[tid];
        unsigned int prev = (tid == 0) ? 0u : sc[tid - 1];
        if (cum >= (unsigned)kRem && prev < (unsigned)kRem) { sh_dig = (unsigned)tid; sh_below = prev; }
        __syncthreads();
        pref = (pref << 8) | sh_dig;
        kRem -= (int)sh_below;
        __syncthreads();
    }
    const unsigned int T = pref;
    const int r = kRem;

    unsigned int eqc = 0;
#pragma unroll
    for (int e = 0; e < 4; e++) eqc += (uk[e] == T);
    sc[tid] = eqc;
    __syncthreads();
    for (int off = 1; off < 256; off <<= 1) {
        unsigned int add = (tid >= off) ? sc[tid - off] : 0u;
        __syncthreads();
        sc[tid] += add;
        __syncthreads();
    }
    const unsigned int baseEq = sc[tid] - eqc;

    float sum = 0.0f;
    {
        unsigned int o = 0;
#pragma unroll
        for (int e = 0; e < 4; e++) {
            bool isEq = (uk[e] == T);
            bool sel  = (uk[e] < T) || (isEq && (baseEq + o) < (unsigned)r);
            if (isEq) o++;
            if (sel) sum += yv[e];
        }
    }
    float tot = block_reduce_256(sum, sredf);
    if (tid == 0) smu = tot / (float)CEM_NE;
    __syncthreads();
    const float mu = smu;

    float ss = 0.0f;
    {
        unsigned int o = 0;
#pragma unroll
        for (int e = 0; e < 4; e++) {
            bool isEq = (uk[e] == T);
            bool sel  = (uk[e] < T) || (isEq && (baseEq + o) < (unsigned)r);
            if (isEq) o++;
            if (sel) { float d = yv[e] - mu; ss = fmaf(d, d, ss); }
        }
    }
    float sst = block_reduce_256(ss, sredf);
    if (tid == 0) {
        g_mu[b]    = mu;
        g_sigma[b] = sqrtf(sst / (float)CEM_NE);
    }
}

// ---------------- final: yhat + diag-Gaussian samples ----------------
__global__ void sample_kernel(uint32_t k0, uint32_t k1, float* __restrict__ out) {
    int gid = blockIdx.x * blockDim.x + threadIdx.x;
    if (gid >= TOTAL) return;
    int b = gid & (NBATCH - 1);
    float eps = bits_to_normal(tf_bits32(k0, k1, (uint32_t)gid));
    float mu = g_mu[b], sg = g_sigma[b];
    float cov = sg * sg;
    cov = fminf(fmaxf(cov, 1e-3f), 100.0f);
    out[NBATCH + gid] = mu + sqrtf(cov) * eps;
    if (gid < NBATCH) out[gid] = g_mu[gid];
}

// ---------------- launch ----------------
extern "C" void kernel_launch(void* const* d_in, const int* in_sizes, int n_in,
                              void* d_out, int out_size)
{
    const float* x  = (const float*)d_in[0];
    const float* W1 = (const float*)d_in[1];
    const float* b1 = (const float*)d_in[2];
    const float* W2 = (const float*)d_in[3];
    const float* b2 = (const float*)d_in[4];
    const float* W3 = (const float*)d_in[5];
    const float* b3 = (const float*)d_in[6];
    float* out = (float*)d_out;

    // JAX partitionable-mode key derivation
    uint32_t cem0 = 0u, cem1 = 0u; threefry2x32(0u, 42u, cem0, cem1);   // split(key,2)[0]
    uint32_t smp0 = 0u, smp1 = 1u; threefry2x32(0u, 42u, smp0, smp1);   // split(key,2)[1]

    uint32_t ik0[CEM_NI], ik1[CEM_NI];
    for (int i = 0; i < CEM_NI; i++) {
        uint32_t a = 0u, c = (uint32_t)i;
        threefry2x32(cem0, cem1, a, c);
        ik0[i] = a; ik1[i] = c;
    }

    const int SMEM_BYTES = 8 * 16 * 32 * (int)sizeof(uint4);   // 65,536 B
    cudaFuncSetAttribute(energy_kernel, cudaFuncAttributeMaxDynamicSharedMemorySize, SMEM_BYTES);

    w2prep_kernel<<<(8 * 16 * 32 + 255) / 256, 256>>>(W2);
    init_kernel<<<(NBATCH + 255) / 256, 256>>>();

    for (int i = 0; i < CEM_NI; i++) {
        energy_kernel<<<TOTAL / 128, 256, SMEM_BYTES>>>(ik0[i], ik1[i], x, W1, b1, b2, W3, b3);
        topk_kernel<<<NBATCH, 256>>>();
    }

    sample_kernel<<<(TOTAL + 255) / 256, 256>>>(smp0, smp1, out);
}